// round 2
// baseline (speedup 1.0000x reference)
#include <cuda_runtime.h>
#include <cuda_bf16.h>

// Problem constants
#define BATCH 4
#define SEQ   2048
#define DMODEL 1024
#define NHEADS 16
#define DHEAD 64
#define MTOT (BATCH*SEQ)          // 8192
#define BHTOT (BATCH*NHEADS)      // 64

// Scratch (device globals: allowed; no cudaMalloc anywhere)
__device__ float g_Q[BHTOT * SEQ * DHEAD];   // (bh, t, d)
__device__ float g_K[BHTOT * SEQ * DHEAD];
__device__ float g_V[BHTOT * SEQ * DHEAD];
__device__ float g_AO[MTOT * DMODEL];        // (b*T+t, D) concat heads

// ---------------------------------------------------------------------------
// GEMM: C[m,n] = sum_k A[m,k] * W[n,k]   (A: MTOT x 1024, W: 1024 x 1024)
// 128x128 tile, BK=16, 256 threads, 8x8 per thread, double buffered.
// MODE 0: scatter to (bh, t, dhead) layout. MODE 1: plain row-major to C.
// ---------------------------------------------------------------------------
#define BM 128
#define BN 128
#define BK 16

template<int MODE>
__device__ __forceinline__ void gemm_core(const float* __restrict__ A,
                                          const float* __restrict__ W,
                                          float* __restrict__ C)
{
    __shared__ __align__(16) float As[2][BK][BM];
    __shared__ __align__(16) float Ws[2][BK][BN];

    const int tid = threadIdx.x;
    const int tx = tid & 15;
    const int ty = tid >> 4;
    const int m0 = blockIdx.y * BM;
    const int n0 = blockIdx.x * BN;

    // load mapping: each thread loads rows r0 and r0+64, 4 consecutive k's
    const int r0 = tid >> 2;            // 0..63
    const int k4 = (tid & 3) << 2;      // 0,4,8,12

    float acc[8][8];
#pragma unroll
    for (int i = 0; i < 8; i++)
#pragma unroll
        for (int j = 0; j < 8; j++) acc[i][j] = 0.f;

    // prologue: tile 0
    {
        const float* Ap = A + (size_t)(m0 + r0) * DMODEL + k4;
        const float* Wp = W + (size_t)(n0 + r0) * DMODEL + k4;
        float4 a0 = *(const float4*)Ap;
        float4 a1 = *(const float4*)(Ap + 64 * DMODEL);
        float4 w0 = *(const float4*)Wp;
        float4 w1 = *(const float4*)(Wp + 64 * DMODEL);
        As[0][k4+0][r0] = a0.x; As[0][k4+1][r0] = a0.y; As[0][k4+2][r0] = a0.z; As[0][k4+3][r0] = a0.w;
        As[0][k4+0][r0+64] = a1.x; As[0][k4+1][r0+64] = a1.y; As[0][k4+2][r0+64] = a1.z; As[0][k4+3][r0+64] = a1.w;
        Ws[0][k4+0][r0] = w0.x; Ws[0][k4+1][r0] = w0.y; Ws[0][k4+2][r0] = w0.z; Ws[0][k4+3][r0] = w0.w;
        Ws[0][k4+0][r0+64] = w1.x; Ws[0][k4+1][r0+64] = w1.y; Ws[0][k4+2][r0+64] = w1.z; Ws[0][k4+3][r0+64] = w1.w;
    }
    __syncthreads();

    const int NT = DMODEL / BK;  // 64
    for (int kt = 0; kt < NT; kt++) {
        const int buf = kt & 1;
        float4 a0, a1, w0, w1;
        if (kt < NT - 1) {
            const float* Ap = A + (size_t)(m0 + r0) * DMODEL + (kt + 1) * BK + k4;
            const float* Wp = W + (size_t)(n0 + r0) * DMODEL + (kt + 1) * BK + k4;
            a0 = *(const float4*)Ap;
            a1 = *(const float4*)(Ap + 64 * DMODEL);
            w0 = *(const float4*)Wp;
            w1 = *(const float4*)(Wp + 64 * DMODEL);
        }
#pragma unroll
        for (int k = 0; k < BK; k++) {
            float av[8], wv[8];
            float4 t0 = *(const float4*)&As[buf][k][ty * 8];
            float4 t1 = *(const float4*)&As[buf][k][ty * 8 + 4];
            av[0]=t0.x; av[1]=t0.y; av[2]=t0.z; av[3]=t0.w;
            av[4]=t1.x; av[5]=t1.y; av[6]=t1.z; av[7]=t1.w;
            float4 u0 = *(const float4*)&Ws[buf][k][tx * 8];
            float4 u1 = *(const float4*)&Ws[buf][k][tx * 8 + 4];
            wv[0]=u0.x; wv[1]=u0.y; wv[2]=u0.z; wv[3]=u0.w;
            wv[4]=u1.x; wv[5]=u1.y; wv[6]=u1.z; wv[7]=u1.w;
#pragma unroll
            for (int i = 0; i < 8; i++)
#pragma unroll
                for (int j = 0; j < 8; j++)
                    acc[i][j] = fmaf(av[i], wv[j], acc[i][j]);
        }
        if (kt < NT - 1) {
            const int nb = buf ^ 1;
            As[nb][k4+0][r0] = a0.x; As[nb][k4+1][r0] = a0.y; As[nb][k4+2][r0] = a0.z; As[nb][k4+3][r0] = a0.w;
            As[nb][k4+0][r0+64] = a1.x; As[nb][k4+1][r0+64] = a1.y; As[nb][k4+2][r0+64] = a1.z; As[nb][k4+3][r0+64] = a1.w;
            Ws[nb][k4+0][r0] = w0.x; Ws[nb][k4+1][r0] = w0.y; Ws[nb][k4+2][r0] = w0.z; Ws[nb][k4+3][r0] = w0.w;
            Ws[nb][k4+0][r0+64] = w1.x; Ws[nb][k4+1][r0+64] = w1.y; Ws[nb][k4+2][r0+64] = w1.z; Ws[nb][k4+3][r0+64] = w1.w;
            __syncthreads();
        }
    }

    // epilogue
    if (MODE == 0) {
#pragma unroll
        for (int i = 0; i < 8; i++) {
            const int m = m0 + ty * 8 + i;
            const int b = m >> 11;          // /2048
            const int t = m & 2047;
#pragma unroll
            for (int j = 0; j < 8; j++) {
                const int n = n0 + tx * 8 + j;
                const int h = n >> 6;
                const int dd = n & 63;
                C[(size_t)((b << 4) + h) * (SEQ * DHEAD) + (size_t)t * DHEAD + dd] = acc[i][j];
            }
        }
    } else {
#pragma unroll
        for (int i = 0; i < 8; i++) {
            float* cp = C + (size_t)(m0 + ty * 8 + i) * DMODEL + n0 + tx * 8;
            float4 v0 = make_float4(acc[i][0], acc[i][1], acc[i][2], acc[i][3]);
            float4 v1 = make_float4(acc[i][4], acc[i][5], acc[i][6], acc[i][7]);
            *(float4*)cp = v0;
            *(float4*)(cp + 4) = v1;
        }
    }
}

__global__ void __launch_bounds__(256) qkv_kernel(const float* __restrict__ x,
                                                  const float* __restrict__ wq,
                                                  const float* __restrict__ wk,
                                                  const float* __restrict__ wv)
{
    const float* W = (blockIdx.z == 0) ? wq : (blockIdx.z == 1) ? wk : wv;
    float* C = (blockIdx.z == 0) ? g_Q : (blockIdx.z == 1) ? g_K : g_V;
    gemm_core<0>(x, W, C);
}

__global__ void __launch_bounds__(256) proj_kernel(const float* __restrict__ wo,
                                                   float* __restrict__ out)
{
    gemm_core<1>(g_AO, wo, out);
}

// ---------------------------------------------------------------------------
// Flash attention, causal. Block: 64 queries x 64 keys per tile, 256 threads.
// Thread (ty,tx) owns rows {ty+16i} and cols {tx+16j}, i,j in 0..3.
// Q is pre-scaled by 1/sqrt(DHEAD) at load; masking only on diagonal tile.
// ---------------------------------------------------------------------------
#define ATT_STRIDE 65
#define SQ(r,d) sm[(r)*ATT_STRIDE + (d)]
#define SK(r,d) sm[64*ATT_STRIDE + (r)*ATT_STRIDE + (d)]
#define SV(r,d) sm[2*64*ATT_STRIDE + (r)*ATT_STRIDE + (d)]
#define SP(r,d) sm[3*64*ATT_STRIDE + (r)*ATT_STRIDE + (d)]
#define ATT_SMEM (4 * 64 * ATT_STRIDE * sizeof(float))

__global__ void __launch_bounds__(256) attn_kernel()
{
    extern __shared__ __align__(16) float sm[];
    const int tid = threadIdx.x;
    const int tx = tid & 15;
    const int ty = tid >> 4;
    const int qt = blockIdx.x;
    const int bh = blockIdx.y;
    const int q0 = qt * 64;

    const float* Qp = g_Q + (size_t)bh * SEQ * DHEAD;
    const float* Kp = g_K + (size_t)bh * SEQ * DHEAD;
    const float* Vp = g_V + (size_t)bh * SEQ * DHEAD;

    const float scale = 0.125f;  // 1/sqrt(64)

    // load Q tile (64x64), pre-scaled
#pragma unroll
    for (int it = 0; it < 4; it++) {
        const int idx = it * 256 + tid;
        const int r = idx >> 4;
        const int d4 = (idx & 15) << 2;
        float4 v = *(const float4*)&Qp[(size_t)(q0 + r) * DHEAD + d4];
        SQ(r, d4 + 0) = v.x * scale; SQ(r, d4 + 1) = v.y * scale;
        SQ(r, d4 + 2) = v.z * scale; SQ(r, d4 + 3) = v.w * scale;
    }

    float o[4][4];
    float mrow[4], lrow[4];
#pragma unroll
    for (int i = 0; i < 4; i++) {
        mrow[i] = -1e30f; lrow[i] = 0.f;
#pragma unroll
        for (int j = 0; j < 4; j++) o[i][j] = 0.f;
    }

    const int nkt = qt + 1;      // causal: only tiles with k0 <= q0+63

    for (int kt = 0; kt < nkt; kt++) {
        const int k0 = kt * 64;
        __syncthreads();   // protect Q(first iter)/Ks/Vs/Ps reuse
#pragma unroll
        for (int it = 0; it < 4; it++) {
            const int idx = it * 256 + tid;
            const int r = idx >> 4;
            const int d4 = (idx & 15) << 2;
            float4 kv = *(const float4*)&Kp[(size_t)(k0 + r) * DHEAD + d4];
            SK(r, d4 + 0) = kv.x; SK(r, d4 + 1) = kv.y; SK(r, d4 + 2) = kv.z; SK(r, d4 + 3) = kv.w;
            float4 vv = *(const float4*)&Vp[(size_t)(k0 + r) * DHEAD + d4];
            SV(r, d4 + 0) = vv.x; SV(r, d4 + 1) = vv.y; SV(r, d4 + 2) = vv.z; SV(r, d4 + 3) = vv.w;
        }
        __syncthreads();

        // S = Q K^T (4x4 per thread)
        float s[4][4];
#pragma unroll
        for (int i = 0; i < 4; i++)
#pragma unroll
            for (int j = 0; j < 4; j++) s[i][j] = 0.f;

#pragma unroll 4
        for (int d = 0; d < 64; d++) {
            float a[4], bq[4];
#pragma unroll
            for (int i = 0; i < 4; i++) a[i] = SQ(ty + 16 * i, d);
#pragma unroll
            for (int j = 0; j < 4; j++) bq[j] = SK(tx + 16 * j, d);
#pragma unroll
            for (int i = 0; i < 4; i++)
#pragma unroll
                for (int j = 0; j < 4; j++)
                    s[i][j] = fmaf(a[i], bq[j], s[i][j]);
        }

        // causal mask: only the diagonal tile needs it
        if (kt == qt) {
#pragma unroll
            for (int i = 0; i < 4; i++) {
                const int qi = ty + 16 * i;
#pragma unroll
                for (int j = 0; j < 4; j++) {
                    const int kj = tx + 16 * j;
                    if (kj > qi) s[i][j] = -1e30f;
                }
            }
        }

        // online softmax per row
#pragma unroll
        for (int i = 0; i < 4; i++) {
            float mx = s[i][0];
            mx = fmaxf(mx, s[i][1]); mx = fmaxf(mx, s[i][2]); mx = fmaxf(mx, s[i][3]);
#pragma unroll
            for (int off = 1; off < 16; off <<= 1)
                mx = fmaxf(mx, __shfl_xor_sync(0xffffffffu, mx, off));
            const float nm = fmaxf(mrow[i], mx);
            float rs = 0.f;
#pragma unroll
            for (int j = 0; j < 4; j++) {
                s[i][j] = __expf(s[i][j] - nm);
                rs += s[i][j];
            }
#pragma unroll
            for (int off = 1; off < 16; off <<= 1)
                rs += __shfl_xor_sync(0xffffffffu, rs, off);
            const float alpha = __expf(mrow[i] - nm);
            lrow[i] = lrow[i] * alpha + rs;
            mrow[i] = nm;
#pragma unroll
            for (int j = 0; j < 4; j++) {
                o[i][j] *= alpha;
                SP(ty + 16 * i, tx + 16 * j) = s[i][j];
            }
        }
        __syncthreads();

        // O += P V
#pragma unroll 4
        for (int c = 0; c < 64; c++) {
            float p[4], v[4];
#pragma unroll
            for (int i = 0; i < 4; i++) p[i] = SP(ty + 16 * i, c);
#pragma unroll
            for (int j = 0; j < 4; j++) v[j] = SV(c, tx + 16 * j);
#pragma unroll
            for (int i = 0; i < 4; i++)
#pragma unroll
                for (int j = 0; j < 4; j++)
                    o[i][j] = fmaf(p[i], v[j], o[i][j]);
        }
    }

    // write attention output to (b, t, h*64+dd) layout
    const int b = bh >> 4;
    const int h = bh & 15;
#pragma unroll
    for (int i = 0; i < 4; i++) {
        const int t = q0 + ty + 16 * i;
        const float inv = 1.f / lrow[i];
        float* ap = g_AO + (size_t)(b * SEQ + t) * DMODEL + h * DHEAD;
#pragma unroll
        for (int j = 0; j < 4; j++)
            ap[tx + 16 * j] = o[i][j] * inv;
    }
}

// ---------------------------------------------------------------------------
extern "C" void kernel_launch(void* const* d_in, const int* in_sizes, int n_in,
                              void* d_out, int out_size)
{
    const float* x  = (const float*)d_in[0];
    const float* wq = (const float*)d_in[1];
    const float* wk = (const float*)d_in[2];
    const float* wv = (const float*)d_in[3];
    const float* wo = (const float*)d_in[4];
    float* out = (float*)d_out;

    static bool attr_set = false;
    if (!attr_set) {
        cudaFuncSetAttribute(attn_kernel, cudaFuncAttributeMaxDynamicSharedMemorySize, (int)ATT_SMEM);
        attr_set = true;
    }

    qkv_kernel<<<dim3(DMODEL / BN, MTOT / BM, 3), 256>>>(x, wq, wk, wv);
    attn_kernel<<<dim3(SEQ / 64, BHTOT), 256, ATT_SMEM>>>();
    proj_kernel<<<dim3(DMODEL / BN, MTOT / BM), 256>>>(wo, out);
}

// round 4
// speedup vs baseline: 1.6959x; 1.6959x over previous
#include <cuda_runtime.h>
#include <cuda_bf16.h>
#include <cstdint>

// Problem constants
#define BATCH 4
#define SEQ   2048
#define DMODEL 1024
#define NHEADS 16
#define DHEAD 64
#define MTOT (BATCH*SEQ)          // 8192
#define BHTOT (BATCH*NHEADS)      // 64

// Scratch: all row-major (b*T+t, D)
__device__ float g_Q[MTOT * DMODEL];
__device__ float g_K[MTOT * DMODEL];
__device__ float g_V[MTOT * DMODEL];
__device__ float g_AO[MTOT * DMODEL];

// ---------------------------------------------------------------------------
// Helpers
// ---------------------------------------------------------------------------
__device__ __forceinline__ uint32_t smem_u32(const void* p) {
    uint32_t a;
    asm("{ .reg .u64 t; cvta.to.shared.u64 t, %1; cvt.u32.u64 %0, t; }" : "=r"(a) : "l"(p));
    return a;
}
__device__ __forceinline__ void cpasync16(uint32_t dst, const void* src) {
    asm volatile("cp.async.cg.shared.global [%0], [%1], 16;" :: "r"(dst), "l"(src));
}
#define CP_COMMIT() asm volatile("cp.async.commit_group;" ::: "memory")
#define CP_WAIT1()  asm volatile("cp.async.wait_group 1;" ::: "memory")
#define CP_WAIT0()  asm volatile("cp.async.wait_group 0;" ::: "memory")

__device__ __forceinline__ uint32_t f2tf32(float f) {
    uint32_t u;
    asm("cvt.rna.tf32.f32 %0, %1;" : "=r"(u) : "f"(f));
    return u;
}
__device__ __forceinline__ void mma_tf32(float c[4], const uint32_t a[4], const uint32_t b[2]) {
    asm volatile("mma.sync.aligned.m16n8k8.row.col.f32.tf32.tf32.f32 "
        "{%0,%1,%2,%3}, {%4,%5,%6,%7}, {%8,%9}, {%0,%1,%2,%3};"
        : "+f"(c[0]), "+f"(c[1]), "+f"(c[2]), "+f"(c[3])
        : "r"(a[0]), "r"(a[1]), "r"(a[2]), "r"(a[3]), "r"(b[0]), "r"(b[1]));
}

// ---------------------------------------------------------------------------
// tf32 mma.sync GEMM:  C[m,n] = sum_k A[m,k] * W[n,k]
// A: MTOT x 1024 (K-major), W: 1024 x 1024 (K-major), C row-major.
// Block 128x128x32, 256 threads (8 warps, warp grid 2m x 4n, warp tile 64x32).
// Smem: XOR-swizzled (float4 chunk c4 ^= row&7), 2-stage cp.async pipeline.
// ---------------------------------------------------------------------------
#define G_BM 128
#define G_BN 128
#define G_BK 32
#define G_NT (DMODEL / G_BK)       // 32
#define TILE_F (G_BM * G_BK)       // 4096 floats = 16KB
#define STAGE_F (2 * TILE_F)       // A + B per stage
#define GEMM_SMEM (2 * STAGE_F * 4)  // 64 KB

// float-index into swizzled tile: row r (0..127), col c (0..31)
#define SMF(base, r, c) smf[(base) + (r) * 32 + (((((c) >> 2) ^ ((r) & 7))) << 2) + ((c) & 3)]

__device__ __forceinline__ void gemm_core(const float* __restrict__ A,
                                          const float* __restrict__ W,
                                          float* __restrict__ C)
{
    extern __shared__ __align__(16) float smf[];
    const uint32_t smb = smem_u32(smf);
    const int tid = threadIdx.x;
    const int wid = tid >> 5;
    const int lane = tid & 31;
    const int gro = lane >> 2;     // 0..7
    const int tig = lane & 3;      // 0..3
    const int wm = wid >> 2;       // 0..1
    const int wn = wid & 3;        // 0..3
    const int m0 = blockIdx.y * G_BM;
    const int n0 = blockIdx.x * G_BN;

    float acc[4][4][4];
#pragma unroll
    for (int mi = 0; mi < 4; mi++)
#pragma unroll
        for (int ni = 0; ni < 4; ni++)
#pragma unroll
            for (int q = 0; q < 4; q++) acc[mi][ni][q] = 0.f;

    // loader: 4 float4 per thread per operand tile
    auto load_tile = [&](int kt, int stage) {
        const int abase = stage * STAGE_F;
        const int bbase = abase + TILE_F;
#pragma unroll
        for (int i = 0; i < 4; i++) {
            const int idx = i * 256 + tid;
            const int row = idx >> 3;
            const int c4 = idx & 7;
            const int sw = ((c4 ^ (row & 7)) << 2);
            const uint32_t afo = (uint32_t)(abase + row * 32 + sw) * 4;
            const uint32_t bfo = (uint32_t)(bbase + row * 32 + sw) * 4;
            cpasync16(smb + afo, A + (size_t)(m0 + row) * DMODEL + kt * G_BK + c4 * 4);
            cpasync16(smb + bfo, W + (size_t)(n0 + row) * DMODEL + kt * G_BK + c4 * 4);
        }
        CP_COMMIT();
    };

    load_tile(0, 0);
    int buf = 0;

    for (int kt = 0; kt < G_NT; kt++) {
        if (kt + 1 < G_NT) { load_tile(kt + 1, buf ^ 1); CP_WAIT1(); }
        else               { CP_WAIT0(); }
        __syncthreads();

        const int aoff = buf * STAGE_F;
        const int boff = aoff + TILE_F;

#pragma unroll
        for (int ks = 0; ks < 4; ks++) {
            const int kc = ks * 8;
            uint32_t af[4][4], bf[4][2];
#pragma unroll
            for (int mi = 0; mi < 4; mi++) {
                const int r = wm * 64 + mi * 16 + gro;
                af[mi][0] = f2tf32(SMF(aoff, r,     kc + tig));
                af[mi][1] = f2tf32(SMF(aoff, r + 8, kc + tig));
                af[mi][2] = f2tf32(SMF(aoff, r,     kc + tig + 4));
                af[mi][3] = f2tf32(SMF(aoff, r + 8, kc + tig + 4));
            }
#pragma unroll
            for (int ni = 0; ni < 4; ni++) {
                const int n = wn * 32 + ni * 8 + gro;
                bf[ni][0] = f2tf32(SMF(boff, n, kc + tig));
                bf[ni][1] = f2tf32(SMF(boff, n, kc + tig + 4));
            }
#pragma unroll
            for (int mi = 0; mi < 4; mi++)
#pragma unroll
                for (int ni = 0; ni < 4; ni++)
                    mma_tf32(acc[mi][ni], af[mi], bf[ni]);
        }
        __syncthreads();
        buf ^= 1;
    }

    // epilogue: float2 stores
#pragma unroll
    for (int mi = 0; mi < 4; mi++) {
        const int r0 = m0 + wm * 64 + mi * 16 + gro;
#pragma unroll
        for (int ni = 0; ni < 4; ni++) {
            const int cc = n0 + wn * 32 + ni * 8 + tig * 2;
            float2 v0 = make_float2(acc[mi][ni][0], acc[mi][ni][1]);
            float2 v1 = make_float2(acc[mi][ni][2], acc[mi][ni][3]);
            *(float2*)&C[(size_t)r0 * DMODEL + cc] = v0;
            *(float2*)&C[(size_t)(r0 + 8) * DMODEL + cc] = v1;
        }
    }
}

__global__ void __launch_bounds__(256) qkv_kernel(const float* __restrict__ x,
                                                  const float* __restrict__ wq,
                                                  const float* __restrict__ wk,
                                                  const float* __restrict__ wv)
{
    const float* W = (blockIdx.z == 0) ? wq : (blockIdx.z == 1) ? wk : wv;
    float* C = (blockIdx.z == 0) ? g_Q : (blockIdx.z == 1) ? g_K : g_V;
    gemm_core(x, W, C);
}

__global__ void __launch_bounds__(256) proj_kernel(const float* __restrict__ wo,
                                                   float* __restrict__ out)
{
    gemm_core(g_AO, wo, out);
}

// ---------------------------------------------------------------------------
// Flash attention (fp32 SIMT), causal. 64x64 tiles, 256 threads.
// Q/K/V row-major (b, t, D): row pitch DMODEL, head offset h*DHEAD.
// ---------------------------------------------------------------------------
#define ATT_STRIDE 65
#define SQ(r,d) sm[(r)*ATT_STRIDE + (d)]
#define SK(r,d) sm[64*ATT_STRIDE + (r)*ATT_STRIDE + (d)]
#define SV(r,d) sm[2*64*ATT_STRIDE + (r)*ATT_STRIDE + (d)]
#define SP(r,d) sm[3*64*ATT_STRIDE + (r)*ATT_STRIDE + (d)]
#define ATT_SMEM (4 * 64 * ATT_STRIDE * sizeof(float))

__global__ void __launch_bounds__(256) attn_kernel()
{
    extern __shared__ __align__(16) float sm[];
    const int tid = threadIdx.x;
    const int tx = tid & 15;
    const int ty = tid >> 4;
    const int qt = blockIdx.x;
    const int bh = blockIdx.y;
    const int q0 = qt * 64;
    const int b = bh >> 4;
    const int h = bh & 15;

    const float* Qb = g_Q + (size_t)(b * SEQ) * DMODEL + h * DHEAD;
    const float* Kb = g_K + (size_t)(b * SEQ) * DMODEL + h * DHEAD;
    const float* Vb = g_V + (size_t)(b * SEQ) * DMODEL + h * DHEAD;

    const float scale = 0.125f;

#pragma unroll
    for (int it = 0; it < 4; it++) {
        const int idx = it * 256 + tid;
        const int r = idx >> 4;
        const int d4 = (idx & 15) << 2;
        float4 v = *(const float4*)&Qb[(size_t)(q0 + r) * DMODEL + d4];
        SQ(r, d4 + 0) = v.x * scale; SQ(r, d4 + 1) = v.y * scale;
        SQ(r, d4 + 2) = v.z * scale; SQ(r, d4 + 3) = v.w * scale;
    }

    float o[4][4];
    float mrow[4], lrow[4];
#pragma unroll
    for (int i = 0; i < 4; i++) {
        mrow[i] = -1e30f; lrow[i] = 0.f;
#pragma unroll
        for (int j = 0; j < 4; j++) o[i][j] = 0.f;
    }

    const int nkt = qt + 1;

    for (int kt = 0; kt < nkt; kt++) {
        const int k0 = kt * 64;
        __syncthreads();
#pragma unroll
        for (int it = 0; it < 4; it++) {
            const int idx = it * 256 + tid;
            const int r = idx >> 4;
            const int d4 = (idx & 15) << 2;
            float4 kv = *(const float4*)&Kb[(size_t)(k0 + r) * DMODEL + d4];
            SK(r, d4 + 0) = kv.x; SK(r, d4 + 1) = kv.y; SK(r, d4 + 2) = kv.z; SK(r, d4 + 3) = kv.w;
            float4 vv = *(const float4*)&Vb[(size_t)(k0 + r) * DMODEL + d4];
            SV(r, d4 + 0) = vv.x; SV(r, d4 + 1) = vv.y; SV(r, d4 + 2) = vv.z; SV(r, d4 + 3) = vv.w;
        }
        __syncthreads();

        float s[4][4];
#pragma unroll
        for (int i = 0; i < 4; i++)
#pragma unroll
            for (int j = 0; j < 4; j++) s[i][j] = 0.f;

#pragma unroll 4
        for (int d = 0; d < 64; d++) {
            float a[4], bq[4];
#pragma unroll
            for (int i = 0; i < 4; i++) a[i] = SQ(ty + 16 * i, d);
#pragma unroll
            for (int j = 0; j < 4; j++) bq[j] = SK(tx + 16 * j, d);
#pragma unroll
            for (int i = 0; i < 4; i++)
#pragma unroll
                for (int j = 0; j < 4; j++)
                    s[i][j] = fmaf(a[i], bq[j], s[i][j]);
        }

        if (kt == qt) {
#pragma unroll
            for (int i = 0; i < 4; i++) {
                const int qi = ty + 16 * i;
#pragma unroll
                for (int j = 0; j < 4; j++)
                    if (tx + 16 * j > qi) s[i][j] = -1e30f;
            }
        }

#pragma unroll
        for (int i = 0; i < 4; i++) {
            float mx = fmaxf(fmaxf(s[i][0], s[i][1]), fmaxf(s[i][2], s[i][3]));
#pragma unroll
            for (int off = 1; off < 16; off <<= 1)
                mx = fmaxf(mx, __shfl_xor_sync(0xffffffffu, mx, off));
            const float nm = fmaxf(mrow[i], mx);
            float rs = 0.f;
#pragma unroll
            for (int j = 0; j < 4; j++) {
                s[i][j] = __expf(s[i][j] - nm);
                rs += s[i][j];
            }
#pragma unroll
            for (int off = 1; off < 16; off <<= 1)
                rs += __shfl_xor_sync(0xffffffffu, rs, off);
            const float alpha = __expf(mrow[i] - nm);
            lrow[i] = lrow[i] * alpha + rs;
            mrow[i] = nm;
#pragma unroll
            for (int j = 0; j < 4; j++) {
                o[i][j] *= alpha;
                SP(ty + 16 * i, tx + 16 * j) = s[i][j];
            }
        }
        __syncthreads();

#pragma unroll 4
        for (int c = 0; c < 64; c++) {
            float p[4], v[4];
#pragma unroll
            for (int i = 0; i < 4; i++) p[i] = SP(ty + 16 * i, c);
#pragma unroll
            for (int j = 0; j < 4; j++) v[j] = SV(c, tx + 16 * j);
#pragma unroll
            for (int i = 0; i < 4; i++)
#pragma unroll
                for (int j = 0; j < 4; j++)
                    o[i][j] = fmaf(p[i], v[j], o[i][j]);
        }
    }

#pragma unroll
    for (int i = 0; i < 4; i++) {
        const int t = q0 + ty + 16 * i;
        const float inv = 1.f / lrow[i];
        float* ap = g_AO + (size_t)(b * SEQ + t) * DMODEL + h * DHEAD;
#pragma unroll
        for (int j = 0; j < 4; j++)
            ap[tx + 16 * j] = o[i][j] * inv;
    }
}

// ---------------------------------------------------------------------------
extern "C" void kernel_launch(void* const* d_in, const int* in_sizes, int n_in,
                              void* d_out, int out_size)
{
    const float* x  = (const float*)d_in[0];
    const float* wq = (const float*)d_in[1];
    const float* wk = (const float*)d_in[2];
    const float* wv = (const float*)d_in[3];
    const float* wo = (const float*)d_in[4];
    float* out = (float*)d_out;

    cudaFuncSetAttribute(qkv_kernel,  cudaFuncAttributeMaxDynamicSharedMemorySize, GEMM_SMEM);
    cudaFuncSetAttribute(proj_kernel, cudaFuncAttributeMaxDynamicSharedMemorySize, GEMM_SMEM);
    cudaFuncSetAttribute(attn_kernel, cudaFuncAttributeMaxDynamicSharedMemorySize, (int)ATT_SMEM);

    qkv_kernel<<<dim3(DMODEL / G_BN, MTOT / G_BM, 3), 256, GEMM_SMEM>>>(x, wq, wk, wv);
    attn_kernel<<<dim3(SEQ / 64, BHTOT), 256, ATT_SMEM>>>();
    proj_kernel<<<dim3(DMODEL / G_BN, MTOT / G_BM), 256, GEMM_SMEM>>>(wo, out);
}

// round 6
// speedup vs baseline: 3.0603x; 1.8045x over previous
#include <cuda_runtime.h>
#include <cuda_bf16.h>
#include <cstdint>

// Problem constants
#define BATCH 4
#define SEQ   2048
#define DMODEL 1024
#define NHEADS 16
#define DHEAD 64
#define MTOT (BATCH*SEQ)          // 8192
#define BHTOT (BATCH*NHEADS)      // 64

// Scratch: all row-major (b*T+t, D)
__device__ float g_Q[MTOT * DMODEL];
__device__ float g_K[MTOT * DMODEL];
__device__ float g_V[MTOT * DMODEL];
__device__ float g_AO[MTOT * DMODEL];

// ---------------------------------------------------------------------------
// Helpers
// ---------------------------------------------------------------------------
__device__ __forceinline__ uint32_t smem_u32(const void* p) {
    uint32_t a;
    asm("{ .reg .u64 t; cvta.to.shared.u64 t, %1; cvt.u32.u64 %0, t; }" : "=r"(a) : "l"(p));
    return a;
}
__device__ __forceinline__ void cpasync16(uint32_t dst, const void* src) {
    asm volatile("cp.async.cg.shared.global [%0], [%1], 16;" :: "r"(dst), "l"(src));
}
#define CP_COMMIT() asm volatile("cp.async.commit_group;" ::: "memory")
#define CP_WAIT1()  asm volatile("cp.async.wait_group 1;" ::: "memory")
#define CP_WAIT0()  asm volatile("cp.async.wait_group 0;" ::: "memory")

__device__ __forceinline__ uint32_t f2tf32(float f) {
    uint32_t u;
    asm("cvt.rna.tf32.f32 %0, %1;" : "=r"(u) : "f"(f));
    return u;
}
__device__ __forceinline__ void mma_tf32(float c[4], const uint32_t a[4], const uint32_t b[2]) {
    asm volatile("mma.sync.aligned.m16n8k8.row.col.f32.tf32.tf32.f32 "
        "{%0,%1,%2,%3}, {%4,%5,%6,%7}, {%8,%9}, {%0,%1,%2,%3};"
        : "+f"(c[0]), "+f"(c[1]), "+f"(c[2]), "+f"(c[3])
        : "r"(a[0]), "r"(a[1]), "r"(a[2]), "r"(a[3]), "r"(b[0]), "r"(b[1]));
}

// ---------------------------------------------------------------------------
// tf32 mma.sync GEMM:  C[m,n] = sum_k A[m,k] * W[n,k]   (unchanged from R4)
// ---------------------------------------------------------------------------
#define G_BM 128
#define G_BN 128
#define G_BK 32
#define G_NT (DMODEL / G_BK)       // 32
#define TILE_F (G_BM * G_BK)       // 4096 floats = 16KB
#define STAGE_F (2 * TILE_F)
#define GEMM_SMEM (2 * STAGE_F * 4)  // 64 KB

#define SMF(base, r, c) smf[(base) + (r) * 32 + (((((c) >> 2) ^ ((r) & 7))) << 2) + ((c) & 3)]

__device__ __forceinline__ void gemm_core(const float* __restrict__ A,
                                          const float* __restrict__ W,
                                          float* __restrict__ C)
{
    extern __shared__ __align__(16) float smf[];
    const uint32_t smb = smem_u32(smf);
    const int tid = threadIdx.x;
    const int wid = tid >> 5;
    const int lane = tid & 31;
    const int gro = lane >> 2;
    const int tig = lane & 3;
    const int wm = wid >> 2;
    const int wn = wid & 3;
    const int m0 = blockIdx.y * G_BM;
    const int n0 = blockIdx.x * G_BN;

    float acc[4][4][4];
#pragma unroll
    for (int mi = 0; mi < 4; mi++)
#pragma unroll
        for (int ni = 0; ni < 4; ni++)
#pragma unroll
            for (int q = 0; q < 4; q++) acc[mi][ni][q] = 0.f;

    auto load_tile = [&](int kt, int stage) {
        const int abase = stage * STAGE_F;
        const int bbase = abase + TILE_F;
#pragma unroll
        for (int i = 0; i < 4; i++) {
            const int idx = i * 256 + tid;
            const int row = idx >> 3;
            const int c4 = idx & 7;
            const int sw = ((c4 ^ (row & 7)) << 2);
            cpasync16(smb + (uint32_t)(abase + row * 32 + sw) * 4,
                      A + (size_t)(m0 + row) * DMODEL + kt * G_BK + c4 * 4);
            cpasync16(smb + (uint32_t)(bbase + row * 32 + sw) * 4,
                      W + (size_t)(n0 + row) * DMODEL + kt * G_BK + c4 * 4);
        }
        CP_COMMIT();
    };

    load_tile(0, 0);
    int buf = 0;

    for (int kt = 0; kt < G_NT; kt++) {
        if (kt + 1 < G_NT) { load_tile(kt + 1, buf ^ 1); CP_WAIT1(); }
        else               { CP_WAIT0(); }
        __syncthreads();

        const int aoff = buf * STAGE_F;
        const int boff = aoff + TILE_F;

#pragma unroll
        for (int ks = 0; ks < 4; ks++) {
            const int kc = ks * 8;
            uint32_t af[4][4], bf[4][2];
#pragma unroll
            for (int mi = 0; mi < 4; mi++) {
                const int r = wm * 64 + mi * 16 + gro;
                af[mi][0] = f2tf32(SMF(aoff, r,     kc + tig));
                af[mi][1] = f2tf32(SMF(aoff, r + 8, kc + tig));
                af[mi][2] = f2tf32(SMF(aoff, r,     kc + tig + 4));
                af[mi][3] = f2tf32(SMF(aoff, r + 8, kc + tig + 4));
            }
#pragma unroll
            for (int ni = 0; ni < 4; ni++) {
                const int n = wn * 32 + ni * 8 + gro;
                bf[ni][0] = f2tf32(SMF(boff, n, kc + tig));
                bf[ni][1] = f2tf32(SMF(boff, n, kc + tig + 4));
            }
#pragma unroll
            for (int mi = 0; mi < 4; mi++)
#pragma unroll
                for (int ni = 0; ni < 4; ni++)
                    mma_tf32(acc[mi][ni], af[mi], bf[ni]);
        }
        __syncthreads();
        buf ^= 1;
    }

#pragma unroll
    for (int mi = 0; mi < 4; mi++) {
        const int r0 = m0 + wm * 64 + mi * 16 + gro;
#pragma unroll
        for (int ni = 0; ni < 4; ni++) {
            const int cc = n0 + wn * 32 + ni * 8 + tig * 2;
            *(float2*)&C[(size_t)r0 * DMODEL + cc] = make_float2(acc[mi][ni][0], acc[mi][ni][1]);
            *(float2*)&C[(size_t)(r0 + 8) * DMODEL + cc] = make_float2(acc[mi][ni][2], acc[mi][ni][3]);
        }
    }
}

__global__ void __launch_bounds__(256) qkv_kernel(const float* __restrict__ x,
                                                  const float* __restrict__ wq,
                                                  const float* __restrict__ wk,
                                                  const float* __restrict__ wv)
{
    const float* W = (blockIdx.z == 0) ? wq : (blockIdx.z == 1) ? wk : wv;
    float* C = (blockIdx.z == 0) ? g_Q : (blockIdx.z == 1) ? g_K : g_V;
    gemm_core(x, W, C);
}

__global__ void __launch_bounds__(256) proj_kernel(const float* __restrict__ wo,
                                                   float* __restrict__ out)
{
    gemm_core(g_AO, wo, out);
}

// ---------------------------------------------------------------------------
// Flash attention with tf32 mma.sync. Causal.
// Block: 64 q-rows x 64 k-cols, 128 threads (4 warps, 16 rows each).
// Smem (floats, stride 68): [Q->P: 64*68][K: 2 stages 64*68][V: 2 stages 64*68]
// Q fragments pre-converted to registers; Q smem region reused as P tile.
// ---------------------------------------------------------------------------
#define AST 68
#define ATT_TILE_F (64 * AST)                      // 4352 floats
#define ATT_SMEM (5 * ATT_TILE_F * 4)              // 87040 B

__global__ void __launch_bounds__(128) attn_kernel()
{
    extern __shared__ __align__(16) float sm[];
    float* s_qp = sm;                   // Q, later P
    float* s_k  = sm + ATT_TILE_F;      // 2 stages
    float* s_v  = sm + 3 * ATT_TILE_F;  // 2 stages
    const uint32_t smb_k = smem_u32(s_k);
    const uint32_t smb_v = smem_u32(s_v);

    const int tid = threadIdx.x;
    const int wid = tid >> 5;
    const int lane = tid & 31;
    const int gro = lane >> 2;
    const int tig = lane & 3;
    const int rq = wid * 16;            // warp's row base in tile

    const int qt = blockIdx.x;
    const int bh = blockIdx.y;
    const int q0 = qt * 64;
    const int b = bh >> 4;
    const int h = bh & 15;

    const float* Qb = g_Q + (size_t)(b * SEQ) * DMODEL + h * DHEAD;
    const float* Kb = g_K + (size_t)(b * SEQ) * DMODEL + h * DHEAD;
    const float* Vb = g_V + (size_t)(b * SEQ) * DMODEL + h * DHEAD;

    // ---- load Q tile (scaled by 1/8) into smem ----
#pragma unroll
    for (int i = 0; i < 8; i++) {
        const int idx = i * 128 + tid;
        const int r = idx >> 4;
        const int c4 = idx & 15;
        float4 v = *(const float4*)&Qb[(size_t)(q0 + r) * DMODEL + c4 * 4];
        float* dst = &s_qp[r * AST + c4 * 4];
        dst[0] = v.x * 0.125f; dst[1] = v.y * 0.125f;
        dst[2] = v.z * 0.125f; dst[3] = v.w * 0.125f;
    }
    __syncthreads();

    // ---- pre-convert Q fragments to registers (8 k-steps x 4) ----
    uint32_t qf[8][4];
#pragma unroll
    for (int ks = 0; ks < 8; ks++) {
        qf[ks][0] = f2tf32(s_qp[(rq + gro) * AST + ks * 8 + tig]);
        qf[ks][1] = f2tf32(s_qp[(rq + gro + 8) * AST + ks * 8 + tig]);
        qf[ks][2] = f2tf32(s_qp[(rq + gro) * AST + ks * 8 + tig + 4]);
        qf[ks][3] = f2tf32(s_qp[(rq + gro + 8) * AST + ks * 8 + tig + 4]);
    }

    // ---- KV tile loader (cp.async) ----
    auto load_kv = [&](int kt, int stage) {
        const int k0 = kt * 64;
        const float* Kp = Kb + (size_t)k0 * DMODEL;
        const float* Vp = Vb + (size_t)k0 * DMODEL;
        const uint32_t so = (uint32_t)(stage * ATT_TILE_F) * 4;
#pragma unroll
        for (int i = 0; i < 8; i++) {
            const int idx = i * 128 + tid;
            const int r = idx >> 4;
            const int c4 = idx & 15;
            const uint32_t off = so + (uint32_t)(r * AST + c4 * 4) * 4;
            cpasync16(smb_k + off, Kp + (size_t)r * DMODEL + c4 * 4);
            cpasync16(smb_v + off, Vp + (size_t)r * DMODEL + c4 * 4);
        }
        CP_COMMIT();
    };

    // ---- state ----
    float o[8][4];
#pragma unroll
    for (int nt = 0; nt < 8; nt++)
#pragma unroll
        for (int q = 0; q < 4; q++) o[nt][q] = 0.f;
    float m0 = -1e30f, m1 = -1e30f, l0 = 0.f, l1 = 0.f;

    load_kv(0, 0);
    int buf = 0;

    for (int kt = 0; kt <= qt; kt++) {
        if (kt < qt) { load_kv(kt + 1, buf ^ 1); CP_WAIT1(); }
        else         { CP_WAIT0(); }
        __syncthreads();

        const float* kb = s_k + buf * ATT_TILE_F;
        const float* vb = s_v + buf * ATT_TILE_F;

        // ---- S = Q K^T ----
        float s[8][4];
#pragma unroll
        for (int nt = 0; nt < 8; nt++)
#pragma unroll
            for (int q = 0; q < 4; q++) s[nt][q] = 0.f;

#pragma unroll
        for (int ks = 0; ks < 8; ks++) {
#pragma unroll
            for (int nt = 0; nt < 8; nt++) {
                uint32_t bk[2];
                bk[0] = f2tf32(kb[(nt * 8 + gro) * AST + ks * 8 + tig]);
                bk[1] = f2tf32(kb[(nt * 8 + gro) * AST + ks * 8 + tig + 4]);
                mma_tf32(s[nt], qf[ks], bk);
            }
        }

        // ---- causal mask (diagonal tile only) ----
        if (kt == qt) {
            const int r0 = rq + gro, r1 = rq + gro + 8;
#pragma unroll
            for (int nt = 0; nt < 8; nt++) {
                const int c0 = nt * 8 + tig * 2;
                if (c0 > r0)     s[nt][0] = -1e30f;
                if (c0 + 1 > r0) s[nt][1] = -1e30f;
                if (c0 > r1)     s[nt][2] = -1e30f;
                if (c0 + 1 > r1) s[nt][3] = -1e30f;
            }
        }

        // ---- online softmax on fragments ----
        float mx0 = -1e30f, mx1 = -1e30f;
#pragma unroll
        for (int nt = 0; nt < 8; nt++) {
            mx0 = fmaxf(mx0, fmaxf(s[nt][0], s[nt][1]));
            mx1 = fmaxf(mx1, fmaxf(s[nt][2], s[nt][3]));
        }
        mx0 = fmaxf(mx0, __shfl_xor_sync(0xffffffffu, mx0, 1));
        mx0 = fmaxf(mx0, __shfl_xor_sync(0xffffffffu, mx0, 2));
        mx1 = fmaxf(mx1, __shfl_xor_sync(0xffffffffu, mx1, 1));
        mx1 = fmaxf(mx1, __shfl_xor_sync(0xffffffffu, mx1, 2));

        const float nm0 = fmaxf(m0, mx0);
        const float nm1 = fmaxf(m1, mx1);
        const float a0 = __expf(m0 - nm0);
        const float a1 = __expf(m1 - nm1);
        m0 = nm0; m1 = nm1;

        float rs0 = 0.f, rs1 = 0.f;
#pragma unroll
        for (int nt = 0; nt < 8; nt++) {
            s[nt][0] = __expf(s[nt][0] - nm0); rs0 += s[nt][0];
            s[nt][1] = __expf(s[nt][1] - nm0); rs0 += s[nt][1];
            s[nt][2] = __expf(s[nt][2] - nm1); rs1 += s[nt][2];
            s[nt][3] = __expf(s[nt][3] - nm1); rs1 += s[nt][3];
        }
        rs0 += __shfl_xor_sync(0xffffffffu, rs0, 1);
        rs0 += __shfl_xor_sync(0xffffffffu, rs0, 2);
        rs1 += __shfl_xor_sync(0xffffffffu, rs1, 1);
        rs1 += __shfl_xor_sync(0xffffffffu, rs1, 2);
        l0 = l0 * a0 + rs0;
        l1 = l1 * a1 + rs1;

        // rescale O, stage P to smem (own warp rows only)
#pragma unroll
        for (int nt = 0; nt < 8; nt++) {
            o[nt][0] *= a0; o[nt][1] *= a0; o[nt][2] *= a1; o[nt][3] *= a1;
            *(float2*)&s_qp[(rq + gro) * AST + nt * 8 + tig * 2] = make_float2(s[nt][0], s[nt][1]);
            *(float2*)&s_qp[(rq + gro + 8) * AST + nt * 8 + tig * 2] = make_float2(s[nt][2], s[nt][3]);
        }
        __syncwarp();

        // ---- O += P V ----
#pragma unroll
        for (int ks = 0; ks < 8; ks++) {
            uint32_t ap[4];
            ap[0] = f2tf32(s_qp[(rq + gro) * AST + ks * 8 + tig]);
            ap[1] = f2tf32(s_qp[(rq + gro + 8) * AST + ks * 8 + tig]);
            ap[2] = f2tf32(s_qp[(rq + gro) * AST + ks * 8 + tig + 4]);
            ap[3] = f2tf32(s_qp[(rq + gro + 8) * AST + ks * 8 + tig + 4]);
#pragma unroll
            for (int nt = 0; nt < 8; nt++) {
                uint32_t bv[2];
                bv[0] = f2tf32(vb[(ks * 8 + tig) * AST + nt * 8 + gro]);
                bv[1] = f2tf32(vb[(ks * 8 + tig + 4) * AST + nt * 8 + gro]);
                mma_tf32(o[nt], ap, bv);
            }
        }

        __syncthreads();
        buf ^= 1;
    }

    // ---- finalize + write (b*T+t, D) ----
    const float inv0 = 1.f / l0;
    const float inv1 = 1.f / l1;
    float* ao0 = g_AO + (size_t)(b * SEQ + q0 + rq + gro) * DMODEL + h * DHEAD;
    float* ao1 = g_AO + (size_t)(b * SEQ + q0 + rq + gro + 8) * DMODEL + h * DHEAD;
#pragma unroll
    for (int nt = 0; nt < 8; nt++) {
        const int cc = nt * 8 + tig * 2;
        *(float2*)&ao0[cc] = make_float2(o[nt][0] * inv0, o[nt][1] * inv0);
        *(float2*)&ao1[cc] = make_float2(o[nt][2] * inv1, o[nt][3] * inv1);
    }
}

// ---------------------------------------------------------------------------
extern "C" void kernel_launch(void* const* d_in, const int* in_sizes, int n_in,
                              void* d_out, int out_size)
{
    const float* x  = (const float*)d_in[0];
    const float* wq = (const float*)d_in[1];
    const float* wk = (const float*)d_in[2];
    const float* wv = (const float*)d_in[3];
    const float* wo = (const float*)d_in[4];
    float* out = (float*)d_out;

    cudaFuncSetAttribute(qkv_kernel,  cudaFuncAttributeMaxDynamicSharedMemorySize, GEMM_SMEM);
    cudaFuncSetAttribute(proj_kernel, cudaFuncAttributeMaxDynamicSharedMemorySize, GEMM_SMEM);
    cudaFuncSetAttribute(attn_kernel, cudaFuncAttributeMaxDynamicSharedMemorySize, ATT_SMEM);

    qkv_kernel<<<dim3(DMODEL / G_BN, MTOT / G_BM, 3), 256, GEMM_SMEM>>>(x, wq, wk, wv);
    attn_kernel<<<dim3(SEQ / 64, BHTOT), 128, ATT_SMEM>>>();
    proj_kernel<<<dim3(DMODEL / G_BN, MTOT / G_BM), 256, GEMM_SMEM>>>(wo, out);
}

// round 7
// speedup vs baseline: 3.9678x; 1.2965x over previous
#include <cuda_runtime.h>
#include <cuda_bf16.h>
#include <cstdint>

// Problem constants
#define BATCH 4
#define SEQ   2048
#define DMODEL 1024
#define NHEADS 16
#define DHEAD 64
#define MTOT (BATCH*SEQ)          // 8192
#define BHTOT (BATCH*NHEADS)      // 64

// Scratch (device globals)
__device__ float g_Q[MTOT * DMODEL];
__device__ float g_K[MTOT * DMODEL];
__device__ float g_V[MTOT * DMODEL];
__device__ float g_AO[MTOT * DMODEL];
__device__ float g_Xr[MTOT * DMODEL];            // tf32-rounded x
__device__ float g_Wr[4][DMODEL * DMODEL];       // tf32-rounded wq,wk,wv,wo

// ---------------------------------------------------------------------------
// Helpers
// ---------------------------------------------------------------------------
__device__ __forceinline__ uint32_t smem_u32(const void* p) {
    uint32_t a;
    asm("{ .reg .u64 t; cvta.to.shared.u64 t, %1; cvt.u32.u64 %0, t; }" : "=r"(a) : "l"(p));
    return a;
}
__device__ __forceinline__ void cpasync16(uint32_t dst, const void* src) {
    asm volatile("cp.async.cg.shared.global [%0], [%1], 16;" :: "r"(dst), "l"(src));
}
#define CP_COMMIT() asm volatile("cp.async.commit_group;" ::: "memory")
#define CP_WAIT1()  asm volatile("cp.async.wait_group 1;" ::: "memory")
#define CP_WAIT0()  asm volatile("cp.async.wait_group 0;" ::: "memory")

__device__ __forceinline__ uint32_t f2tf32(float f) {
    uint32_t u;
    asm("cvt.rna.tf32.f32 %0, %1;" : "=r"(u) : "f"(f));
    return u;
}
__device__ __forceinline__ float roundtf(float f) { return __uint_as_float(f2tf32(f)); }

__device__ __forceinline__ void mma_tf32(float c[4], const uint32_t a[4], const uint32_t b[2]) {
    asm volatile("mma.sync.aligned.m16n8k8.row.col.f32.tf32.tf32.f32 "
        "{%0,%1,%2,%3}, {%4,%5,%6,%7}, {%8,%9}, {%0,%1,%2,%3};"
        : "+f"(c[0]), "+f"(c[1]), "+f"(c[2]), "+f"(c[3])
        : "r"(a[0]), "r"(a[1]), "r"(a[2]), "r"(a[3]), "r"(b[0]), "r"(b[1]));
}

// ---------------------------------------------------------------------------
// Prep: round x + weights to tf32 (rna) once.
// ---------------------------------------------------------------------------
#define XN4 ((int)(MTOT * DMODEL / 4))           // 2M float4
#define WN4 ((int)(DMODEL * DMODEL / 4))         // 262144 float4
#define PREP_TOT (XN4 + 4 * WN4)

__global__ void __launch_bounds__(256) prep_kernel(const float* __restrict__ x,
                                                   const float* __restrict__ wq,
                                                   const float* __restrict__ wk,
                                                   const float* __restrict__ wv,
                                                   const float* __restrict__ wo)
{
    const int i = blockIdx.x * 256 + threadIdx.x;
    if (i >= PREP_TOT) return;
    const float4* src;
    float4* dst;
    int off;
    if (i < XN4) {
        src = (const float4*)x; dst = (float4*)g_Xr; off = i;
    } else {
        const int j = i - XN4;
        const int w = j / WN4;
        off = j - w * WN4;
        src = (const float4*)((w == 0) ? wq : (w == 1) ? wk : (w == 2) ? wv : wo);
        dst = (float4*)g_Wr[w];
    }
    float4 v = src[off];
    v.x = roundtf(v.x); v.y = roundtf(v.y); v.z = roundtf(v.z); v.w = roundtf(v.w);
    dst[off] = v;
}

// ---------------------------------------------------------------------------
// tf32 mma.sync GEMM:  C[m,n] = sum_k A[m,k] * W[n,k]
// Inputs pre-rounded to tf32 -> raw-bit fragment loads (no cvt in loop).
// ROUND_OUT: round C before store (for downstream MMA consumers).
// ---------------------------------------------------------------------------
#define G_BM 128
#define G_BN 128
#define G_BK 32
#define G_NT (DMODEL / G_BK)       // 32
#define TILE_F (G_BM * G_BK)       // 4096 floats = 16KB
#define STAGE_F (2 * TILE_F)
#define GEMM_SMEM (2 * STAGE_F * 4)  // 64 KB

#define SMF(base, r, c) smf[(base) + (r) * 32 + (((((c) >> 2) ^ ((r) & 7))) << 2) + ((c) & 3)]

template<int ROUND_OUT>
__device__ __forceinline__ void gemm_core(const float* __restrict__ A,
                                          const float* __restrict__ W,
                                          float* __restrict__ C)
{
    extern __shared__ __align__(16) float smf[];
    const uint32_t smb = smem_u32(smf);
    const int tid = threadIdx.x;
    const int wid = tid >> 5;
    const int lane = tid & 31;
    const int gro = lane >> 2;
    const int tig = lane & 3;
    const int wm = wid >> 2;
    const int wn = wid & 3;
    const int m0 = blockIdx.y * G_BM;
    const int n0 = blockIdx.x * G_BN;

    float acc[4][4][4];
#pragma unroll
    for (int mi = 0; mi < 4; mi++)
#pragma unroll
        for (int ni = 0; ni < 4; ni++)
#pragma unroll
            for (int q = 0; q < 4; q++) acc[mi][ni][q] = 0.f;

    auto load_tile = [&](int kt, int stage) {
        const int abase = stage * STAGE_F;
        const int bbase = abase + TILE_F;
#pragma unroll
        for (int i = 0; i < 4; i++) {
            const int idx = i * 256 + tid;
            const int row = idx >> 3;
            const int c4 = idx & 7;
            const int sw = ((c4 ^ (row & 7)) << 2);
            cpasync16(smb + (uint32_t)(abase + row * 32 + sw) * 4,
                      A + (size_t)(m0 + row) * DMODEL + kt * G_BK + c4 * 4);
            cpasync16(smb + (uint32_t)(bbase + row * 32 + sw) * 4,
                      W + (size_t)(n0 + row) * DMODEL + kt * G_BK + c4 * 4);
        }
        CP_COMMIT();
    };

    load_tile(0, 0);
    int buf = 0;

    for (int kt = 0; kt < G_NT; kt++) {
        if (kt + 1 < G_NT) { load_tile(kt + 1, buf ^ 1); CP_WAIT1(); }
        else               { CP_WAIT0(); }
        __syncthreads();

        const int aoff = buf * STAGE_F;
        const int boff = aoff + TILE_F;

#pragma unroll
        for (int ks = 0; ks < 4; ks++) {
            const int kc = ks * 8;
            uint32_t af[4][4], bf[4][2];
#pragma unroll
            for (int mi = 0; mi < 4; mi++) {
                const int r = wm * 64 + mi * 16 + gro;
                af[mi][0] = __float_as_uint(SMF(aoff, r,     kc + tig));
                af[mi][1] = __float_as_uint(SMF(aoff, r + 8, kc + tig));
                af[mi][2] = __float_as_uint(SMF(aoff, r,     kc + tig + 4));
                af[mi][3] = __float_as_uint(SMF(aoff, r + 8, kc + tig + 4));
            }
#pragma unroll
            for (int ni = 0; ni < 4; ni++) {
                const int n = wn * 32 + ni * 8 + gro;
                bf[ni][0] = __float_as_uint(SMF(boff, n, kc + tig));
                bf[ni][1] = __float_as_uint(SMF(boff, n, kc + tig + 4));
            }
#pragma unroll
            for (int mi = 0; mi < 4; mi++)
#pragma unroll
                for (int ni = 0; ni < 4; ni++)
                    mma_tf32(acc[mi][ni], af[mi], bf[ni]);
        }
        __syncthreads();
        buf ^= 1;
    }

#pragma unroll
    for (int mi = 0; mi < 4; mi++) {
        const int r0 = m0 + wm * 64 + mi * 16 + gro;
#pragma unroll
        for (int ni = 0; ni < 4; ni++) {
            const int cc = n0 + wn * 32 + ni * 8 + tig * 2;
            float v0 = acc[mi][ni][0], v1 = acc[mi][ni][1];
            float v2 = acc[mi][ni][2], v3 = acc[mi][ni][3];
            if (ROUND_OUT) { v0 = roundtf(v0); v1 = roundtf(v1); v2 = roundtf(v2); v3 = roundtf(v3); }
            *(float2*)&C[(size_t)r0 * DMODEL + cc] = make_float2(v0, v1);
            *(float2*)&C[(size_t)(r0 + 8) * DMODEL + cc] = make_float2(v2, v3);
        }
    }
}

__global__ void __launch_bounds__(256) qkv_kernel()
{
    const float* W = g_Wr[blockIdx.z];
    float* C = (blockIdx.z == 0) ? g_Q : (blockIdx.z == 1) ? g_K : g_V;
    gemm_core<1>(g_Xr, W, C);
}

__global__ void __launch_bounds__(256) proj_kernel(float* __restrict__ out)
{
    gemm_core<0>(g_AO, g_Wr[3], out);
}

// ---------------------------------------------------------------------------
// Flash attention with tf32 mma.sync. Causal. All operands pre-rounded.
// Block: 64 q-rows x 64 k-cols, 128 threads (4 warps, 16 rows each).
// ---------------------------------------------------------------------------
#define AST 68
#define ATT_TILE_F (64 * AST)                      // 4352 floats
#define ATT_SMEM (5 * ATT_TILE_F * 4)              // 87040 B

__global__ void __launch_bounds__(128) attn_kernel()
{
    extern __shared__ __align__(16) float sm[];
    float* s_qp = sm;                   // Q, later P
    float* s_k  = sm + ATT_TILE_F;      // 2 stages
    float* s_v  = sm + 3 * ATT_TILE_F;  // 2 stages
    const uint32_t smb_k = smem_u32(s_k);
    const uint32_t smb_v = smem_u32(s_v);

    const int tid = threadIdx.x;
    const int wid = tid >> 5;
    const int lane = tid & 31;
    const int gro = lane >> 2;
    const int tig = lane & 3;
    const int rq = wid * 16;

    const int qt = blockIdx.x;
    const int bh = blockIdx.y;
    const int q0 = qt * 64;
    const int b = bh >> 4;
    const int h = bh & 15;

    const float* Qb = g_Q + (size_t)(b * SEQ) * DMODEL + h * DHEAD;
    const float* Kb = g_K + (size_t)(b * SEQ) * DMODEL + h * DHEAD;
    const float* Vb = g_V + (size_t)(b * SEQ) * DMODEL + h * DHEAD;

    // ---- load Q tile (scaled by exact 1/8; stays tf32-clean) ----
#pragma unroll
    for (int i = 0; i < 8; i++) {
        const int idx = i * 128 + tid;
        const int r = idx >> 4;
        const int c4 = idx & 15;
        float4 v = *(const float4*)&Qb[(size_t)(q0 + r) * DMODEL + c4 * 4];
        float* dst = &s_qp[r * AST + c4 * 4];
        dst[0] = v.x * 0.125f; dst[1] = v.y * 0.125f;
        dst[2] = v.z * 0.125f; dst[3] = v.w * 0.125f;
    }
    __syncthreads();

    // ---- pre-load Q fragments (raw bits; data pre-rounded) ----
    uint32_t qf[8][4];
#pragma unroll
    for (int ks = 0; ks < 8; ks++) {
        qf[ks][0] = __float_as_uint(s_qp[(rq + gro) * AST + ks * 8 + tig]);
        qf[ks][1] = __float_as_uint(s_qp[(rq + gro + 8) * AST + ks * 8 + tig]);
        qf[ks][2] = __float_as_uint(s_qp[(rq + gro) * AST + ks * 8 + tig + 4]);
        qf[ks][3] = __float_as_uint(s_qp[(rq + gro + 8) * AST + ks * 8 + tig + 4]);
    }

    auto load_kv = [&](int kt, int stage) {
        const int k0 = kt * 64;
        const float* Kp = Kb + (size_t)k0 * DMODEL;
        const float* Vp = Vb + (size_t)k0 * DMODEL;
        const uint32_t so = (uint32_t)(stage * ATT_TILE_F) * 4;
#pragma unroll
        for (int i = 0; i < 8; i++) {
            const int idx = i * 128 + tid;
            const int r = idx >> 4;
            const int c4 = idx & 15;
            const uint32_t off = so + (uint32_t)(r * AST + c4 * 4) * 4;
            cpasync16(smb_k + off, Kp + (size_t)r * DMODEL + c4 * 4);
            cpasync16(smb_v + off, Vp + (size_t)r * DMODEL + c4 * 4);
        }
        CP_COMMIT();
    };

    float o[8][4];
#pragma unroll
    for (int nt = 0; nt < 8; nt++)
#pragma unroll
        for (int q = 0; q < 4; q++) o[nt][q] = 0.f;
    float m0 = -1e30f, m1 = -1e30f, l0 = 0.f, l1 = 0.f;

    load_kv(0, 0);
    int buf = 0;

    for (int kt = 0; kt <= qt; kt++) {
        if (kt < qt) { load_kv(kt + 1, buf ^ 1); CP_WAIT1(); }
        else         { CP_WAIT0(); }
        __syncthreads();

        const float* kb = s_k + buf * ATT_TILE_F;
        const float* vb = s_v + buf * ATT_TILE_F;

        // ---- S = Q K^T ----
        float s[8][4];
#pragma unroll
        for (int nt = 0; nt < 8; nt++)
#pragma unroll
            for (int q = 0; q < 4; q++) s[nt][q] = 0.f;

#pragma unroll
        for (int ks = 0; ks < 8; ks++) {
#pragma unroll
            for (int nt = 0; nt < 8; nt++) {
                uint32_t bk[2];
                bk[0] = __float_as_uint(kb[(nt * 8 + gro) * AST + ks * 8 + tig]);
                bk[1] = __float_as_uint(kb[(nt * 8 + gro) * AST + ks * 8 + tig + 4]);
                mma_tf32(s[nt], qf[ks], bk);
            }
        }

        // ---- causal mask (diagonal tile only) ----
        if (kt == qt) {
            const int r0 = rq + gro, r1 = rq + gro + 8;
#pragma unroll
            for (int nt = 0; nt < 8; nt++) {
                const int c0 = nt * 8 + tig * 2;
                if (c0 > r0)     s[nt][0] = -1e30f;
                if (c0 + 1 > r0) s[nt][1] = -1e30f;
                if (c0 > r1)     s[nt][2] = -1e30f;
                if (c0 + 1 > r1) s[nt][3] = -1e30f;
            }
        }

        // ---- online softmax on fragments ----
        float mx0 = -1e30f, mx1 = -1e30f;
#pragma unroll
        for (int nt = 0; nt < 8; nt++) {
            mx0 = fmaxf(mx0, fmaxf(s[nt][0], s[nt][1]));
            mx1 = fmaxf(mx1, fmaxf(s[nt][2], s[nt][3]));
        }
        mx0 = fmaxf(mx0, __shfl_xor_sync(0xffffffffu, mx0, 1));
        mx0 = fmaxf(mx0, __shfl_xor_sync(0xffffffffu, mx0, 2));
        mx1 = fmaxf(mx1, __shfl_xor_sync(0xffffffffu, mx1, 1));
        mx1 = fmaxf(mx1, __shfl_xor_sync(0xffffffffu, mx1, 2));

        const float nm0 = fmaxf(m0, mx0);
        const float nm1 = fmaxf(m1, mx1);
        const float a0 = __expf(m0 - nm0);
        const float a1 = __expf(m1 - nm1);
        m0 = nm0; m1 = nm1;

        float rs0 = 0.f, rs1 = 0.f;
#pragma unroll
        for (int nt = 0; nt < 8; nt++) {
            s[nt][0] = __expf(s[nt][0] - nm0); rs0 += s[nt][0];
            s[nt][1] = __expf(s[nt][1] - nm0); rs0 += s[nt][1];
            s[nt][2] = __expf(s[nt][2] - nm1); rs1 += s[nt][2];
            s[nt][3] = __expf(s[nt][3] - nm1); rs1 += s[nt][3];
        }
        rs0 += __shfl_xor_sync(0xffffffffu, rs0, 1);
        rs0 += __shfl_xor_sync(0xffffffffu, rs0, 2);
        rs1 += __shfl_xor_sync(0xffffffffu, rs1, 1);
        rs1 += __shfl_xor_sync(0xffffffffu, rs1, 2);
        l0 = l0 * a0 + rs0;
        l1 = l1 * a1 + rs1;

        // rescale O; stage tf32-rounded P to smem (own warp rows only)
#pragma unroll
        for (int nt = 0; nt < 8; nt++) {
            o[nt][0] *= a0; o[nt][1] *= a0; o[nt][2] *= a1; o[nt][3] *= a1;
            *(float2*)&s_qp[(rq + gro) * AST + nt * 8 + tig * 2] =
                make_float2(roundtf(s[nt][0]), roundtf(s[nt][1]));
            *(float2*)&s_qp[(rq + gro + 8) * AST + nt * 8 + tig * 2] =
                make_float2(roundtf(s[nt][2]), roundtf(s[nt][3]));
        }
        __syncwarp();

        // ---- O += P V ----
#pragma unroll
        for (int ks = 0; ks < 8; ks++) {
            uint32_t ap[4];
            ap[0] = __float_as_uint(s_qp[(rq + gro) * AST + ks * 8 + tig]);
            ap[1] = __float_as_uint(s_qp[(rq + gro + 8) * AST + ks * 8 + tig]);
            ap[2] = __float_as_uint(s_qp[(rq + gro) * AST + ks * 8 + tig + 4]);
            ap[3] = __float_as_uint(s_qp[(rq + gro + 8) * AST + ks * 8 + tig + 4]);
#pragma unroll
            for (int nt = 0; nt < 8; nt++) {
                uint32_t bv[2];
                bv[0] = __float_as_uint(vb[(ks * 8 + tig) * AST + nt * 8 + gro]);
                bv[1] = __float_as_uint(vb[(ks * 8 + tig + 4) * AST + nt * 8 + gro]);
                mma_tf32(o[nt], ap, bv);
            }
        }

        __syncthreads();
        buf ^= 1;
    }

    // ---- finalize + write rounded AO (proj's A operand) ----
    const float inv0 = 1.f / l0;
    const float inv1 = 1.f / l1;
    float* ao0 = g_AO + (size_t)(b * SEQ + q0 + rq + gro) * DMODEL + h * DHEAD;
    float* ao1 = g_AO + (size_t)(b * SEQ + q0 + rq + gro + 8) * DMODEL + h * DHEAD;
#pragma unroll
    for (int nt = 0; nt < 8; nt++) {
        const int cc = nt * 8 + tig * 2;
        *(float2*)&ao0[cc] = make_float2(roundtf(o[nt][0] * inv0), roundtf(o[nt][1] * inv0));
        *(float2*)&ao1[cc] = make_float2(roundtf(o[nt][2] * inv1), roundtf(o[nt][3] * inv1));
    }
}

// ---------------------------------------------------------------------------
extern "C" void kernel_launch(void* const* d_in, const int* in_sizes, int n_in,
                              void* d_out, int out_size)
{
    const float* x  = (const float*)d_in[0];
    const float* wq = (const float*)d_in[1];
    const float* wk = (const float*)d_in[2];
    const float* wv = (const float*)d_in[3];
    const float* wo = (const float*)d_in[4];
    float* out = (float*)d_out;

    cudaFuncSetAttribute(qkv_kernel,  cudaFuncAttributeMaxDynamicSharedMemorySize, GEMM_SMEM);
    cudaFuncSetAttribute(proj_kernel, cudaFuncAttributeMaxDynamicSharedMemorySize, GEMM_SMEM);
    cudaFuncSetAttribute(attn_kernel, cudaFuncAttributeMaxDynamicSharedMemorySize, ATT_SMEM);

    prep_kernel<<<(PREP_TOT + 255) / 256, 256>>>(x, wq, wk, wv, wo);
    qkv_kernel<<<dim3(DMODEL / G_BN, MTOT / G_BM, 3), 256, GEMM_SMEM>>>();
    attn_kernel<<<dim3(SEQ / 64, BHTOT), 128, ATT_SMEM>>>();
    proj_kernel<<<dim3(DMODEL / G_BN, MTOT / G_BM), 256, GEMM_SMEM>>>(out);
}

// round 9
// speedup vs baseline: 4.0564x; 1.0223x over previous
#include <cuda_runtime.h>
#include <cuda_bf16.h>
#include <cstdint>

// Problem constants
#define BATCH 4
#define SEQ   2048
#define DMODEL 1024
#define NHEADS 16
#define DHEAD 64
#define MTOT (BATCH*SEQ)          // 8192
#define BHTOT (BATCH*NHEADS)      // 64

// Scratch (device globals)
__device__ float g_Q[MTOT * DMODEL];
__device__ float g_K[MTOT * DMODEL];
__device__ float g_V[MTOT * DMODEL];
__device__ float g_AO[MTOT * DMODEL];
__device__ float g_Xr[MTOT * DMODEL];            // tf32-rounded x
__device__ float g_Wr[4][DMODEL * DMODEL];       // tf32-rounded wq,wk,wv,wo

// ---------------------------------------------------------------------------
// Helpers
// ---------------------------------------------------------------------------
__device__ __forceinline__ uint32_t smem_u32(const void* p) {
    uint32_t a;
    asm("{ .reg .u64 t; cvta.to.shared.u64 t, %1; cvt.u32.u64 %0, t; }" : "=r"(a) : "l"(p));
    return a;
}
__device__ __forceinline__ void cpasync16(uint32_t dst, const void* src) {
    asm volatile("cp.async.cg.shared.global [%0], [%1], 16;" :: "r"(dst), "l"(src));
}
#define CP_COMMIT() asm volatile("cp.async.commit_group;" ::: "memory")
#define CP_WAIT1()  asm volatile("cp.async.wait_group 1;" ::: "memory")
#define CP_WAIT0()  asm volatile("cp.async.wait_group 0;" ::: "memory")

__device__ __forceinline__ uint32_t f2tf32(float f) {
    uint32_t u;
    asm("cvt.rna.tf32.f32 %0, %1;" : "=r"(u) : "f"(f));
    return u;
}
__device__ __forceinline__ float roundtf(float f) { return __uint_as_float(f2tf32(f)); }

__device__ __forceinline__ void mma_tf32(float c[4], const uint32_t a[4], const uint32_t b[2]) {
    asm volatile("mma.sync.aligned.m16n8k8.row.col.f32.tf32.tf32.f32 "
        "{%0,%1,%2,%3}, {%4,%5,%6,%7}, {%8,%9}, {%0,%1,%2,%3};"
        : "+f"(c[0]), "+f"(c[1]), "+f"(c[2]), "+f"(c[3])
        : "r"(a[0]), "r"(a[1]), "r"(a[2]), "r"(a[3]), "r"(b[0]), "r"(b[1]));
}
__device__ __forceinline__ void ldsm_x4(uint32_t r[4], uint32_t addr) {
    asm volatile("ldmatrix.sync.aligned.m8n8.x4.shared.b16 {%0,%1,%2,%3}, [%4];"
        : "=r"(r[0]), "=r"(r[1]), "=r"(r[2]), "=r"(r[3]) : "r"(addr));
}

// ---------------------------------------------------------------------------
// Prep: round x + weights to tf32 (rna) once.
// ---------------------------------------------------------------------------
#define XN4 ((int)(MTOT * DMODEL / 4))
#define WN4 ((int)(DMODEL * DMODEL / 4))
#define PREP_TOT (XN4 + 4 * WN4)

__global__ void __launch_bounds__(256) prep_kernel(const float* __restrict__ x,
                                                   const float* __restrict__ wq,
                                                   const float* __restrict__ wk,
                                                   const float* __restrict__ wv,
                                                   const float* __restrict__ wo)
{
    const int i = blockIdx.x * 256 + threadIdx.x;
    if (i >= PREP_TOT) return;
    const float4* src;
    float4* dst;
    int off;
    if (i < XN4) {
        src = (const float4*)x; dst = (float4*)g_Xr; off = i;
    } else {
        const int j = i - XN4;
        const int w = j / WN4;
        off = j - w * WN4;
        src = (const float4*)((w == 0) ? wq : (w == 1) ? wk : (w == 2) ? wv : wo);
        dst = (float4*)g_Wr[w];
    }
    float4 v = src[off];
    v.x = roundtf(v.x); v.y = roundtf(v.y); v.z = roundtf(v.z); v.w = roundtf(v.w);
    dst[off] = v;
}

// ---------------------------------------------------------------------------
// tf32 mma.sync GEMM with ldmatrix fragment loads.
// C[m,n] = sum_k A[m,k] * W[n,k]; inputs pre-rounded to tf32.
// ---------------------------------------------------------------------------
#define G_BM 128
#define G_BN 128
#define G_BK 32
#define G_NT (DMODEL / G_BK)       // 32
#define TILE_F (G_BM * G_BK)       // 4096 floats = 16KB
#define STAGE_F (2 * TILE_F)
#define GEMM_SMEM (2 * STAGE_F * 4)  // 64 KB

template<int ROUND_OUT>
__device__ __forceinline__ void gemm_core(const float* __restrict__ A,
                                          const float* __restrict__ W,
                                          float* __restrict__ C)
{
    extern __shared__ __align__(16) float smf[];
    const uint32_t smb = smem_u32(smf);
    const int tid = threadIdx.x;
    const int wid = tid >> 5;
    const int lane = tid & 31;
    const int gro = lane >> 2;
    const int tig = lane & 3;
    const int wm = wid >> 2;
    const int wn = wid & 3;
    const int m0 = blockIdx.y * G_BM;
    const int n0 = blockIdx.x * G_BN;

    // ldmatrix per-lane row/parity terms
    const int la_row16 = lane & 15;            // A: row offset within 16
    const int la_hb = lane >> 4;               // A: chunk parity group
    const int lb_rsub = ((lane >> 4) << 3) + (lane & 7);  // B: row offset within 16-row pair
    const int lb_hb = (lane >> 3) & 1;         // B: chunk parity group

    float acc[4][4][4];
#pragma unroll
    for (int mi = 0; mi < 4; mi++)
#pragma unroll
        for (int ni = 0; ni < 4; ni++)
#pragma unroll
            for (int q = 0; q < 4; q++) acc[mi][ni][q] = 0.f;

    auto load_tile = [&](int kt, int stage) {
        const int abase = stage * STAGE_F;
        const int bbase = abase + TILE_F;
#pragma unroll
        for (int i = 0; i < 4; i++) {
            const int idx = i * 256 + tid;
            const int row = idx >> 3;
            const int c4 = idx & 7;
            const int sw = ((c4 ^ (row & 7)) << 2);
            cpasync16(smb + (uint32_t)(abase + row * 32 + sw) * 4,
                      A + (size_t)(m0 + row) * DMODEL + kt * G_BK + c4 * 4);
            cpasync16(smb + (uint32_t)(bbase + row * 32 + sw) * 4,
                      W + (size_t)(n0 + row) * DMODEL + kt * G_BK + c4 * 4);
        }
        CP_COMMIT();
    };

    load_tile(0, 0);
    int buf = 0;

    for (int kt = 0; kt < G_NT; kt++) {
        if (kt + 1 < G_NT) { load_tile(kt + 1, buf ^ 1); CP_WAIT1(); }
        else               { CP_WAIT0(); }
        __syncthreads();

        const uint32_t abyte = smb + (uint32_t)(buf * STAGE_F) * 4;
        const uint32_t bbyte = abyte + (uint32_t)TILE_F * 4;

#pragma unroll
        for (int ks = 0; ks < 4; ks++) {
            uint32_t af[4][4], bf[4][2];
#pragma unroll
            for (int mi = 0; mi < 4; mi++) {
                const int row = wm * 64 + mi * 16 + la_row16;
                const uint32_t c = 2 * ks + la_hb;
                ldsm_x4(af[mi], abyte + (uint32_t)row * 128 + ((c ^ (row & 7)) << 4));
            }
#pragma unroll
            for (int np = 0; np < 2; np++) {
                const int row = wn * 32 + np * 16 + lb_rsub;
                const uint32_t c = 2 * ks + lb_hb;
                uint32_t t4[4];
                ldsm_x4(t4, bbyte + (uint32_t)row * 128 + ((c ^ (row & 7)) << 4));
                bf[2 * np][0] = t4[0]; bf[2 * np][1] = t4[1];
                bf[2 * np + 1][0] = t4[2]; bf[2 * np + 1][1] = t4[3];
            }
#pragma unroll
            for (int mi = 0; mi < 4; mi++)
#pragma unroll
                for (int ni = 0; ni < 4; ni++)
                    mma_tf32(acc[mi][ni], af[mi], bf[ni]);
        }
        __syncthreads();
        buf ^= 1;
    }

#pragma unroll
    for (int mi = 0; mi < 4; mi++) {
        const int r0 = m0 + wm * 64 + mi * 16 + gro;
#pragma unroll
        for (int ni = 0; ni < 4; ni++) {
            const int cc = n0 + wn * 32 + ni * 8 + tig * 2;
            float v0 = acc[mi][ni][0], v1 = acc[mi][ni][1];
            float v2 = acc[mi][ni][2], v3 = acc[mi][ni][3];
            if (ROUND_OUT) { v0 = roundtf(v0); v1 = roundtf(v1); v2 = roundtf(v2); v3 = roundtf(v3); }
            *(float2*)&C[(size_t)r0 * DMODEL + cc] = make_float2(v0, v1);
            *(float2*)&C[(size_t)(r0 + 8) * DMODEL + cc] = make_float2(v2, v3);
        }
    }
}

__global__ void __launch_bounds__(256) qkv_kernel()
{
    const float* W = g_Wr[blockIdx.z];
    float* C = (blockIdx.z == 0) ? g_Q : (blockIdx.z == 1) ? g_K : g_V;
    gemm_core<1>(g_Xr, W, C);
}

__global__ void __launch_bounds__(256) proj_kernel(float* __restrict__ out)
{
    gemm_core<0>(g_AO, g_Wr[3], out);
}

// ---------------------------------------------------------------------------
// Flash attention, tf32 mma.sync + ldmatrix, causal.
// Block: 128 q-rows x 64 k-cols per step, 256 threads (8 warps x 16 rows).
// Smem (floats, stride 68): [Q->P: 128*68][K: 2 stages 64*68][V: 2 stages 64*68]
// ---------------------------------------------------------------------------
#define AST 68
#define QP_F (128 * AST)
#define KV_F (64 * AST)
#define ATT_SMEM ((QP_F + 4 * KV_F) * 4)        // 104448 B

__global__ void __launch_bounds__(256) attn_kernel()
{
    extern __shared__ __align__(16) float sm[];
    float* s_qp = sm;                       // Q, later P (128 rows)
    float* s_k  = sm + QP_F;                // 2 stages
    float* s_v  = sm + QP_F + 2 * KV_F;     // 2 stages
    const uint32_t smb_qp = smem_u32(s_qp);
    const uint32_t smb_k  = smem_u32(s_k);
    const uint32_t smb_v  = smem_u32(s_v);

    const int tid = threadIdx.x;
    const int wid = tid >> 5;
    const int lane = tid & 31;
    const int gro = lane >> 2;
    const int tig = lane & 3;
    const int rq = wid * 16;

    const int la_row16 = lane & 15;
    const int la_hb = lane >> 4;
    const int lb_rsub = ((lane >> 4) << 3) + (lane & 7);
    const int lb_hb = (lane >> 3) & 1;

    const int qt = blockIdx.x;              // 0..15
    const int bh = blockIdx.y;
    const int q0 = qt * 128;
    const int b = bh >> 4;
    const int h = bh & 15;

    const float* Qb = g_Q + (size_t)(b * SEQ) * DMODEL + h * DHEAD;
    const float* Kb = g_K + (size_t)(b * SEQ) * DMODEL + h * DHEAD;
    const float* Vb = g_V + (size_t)(b * SEQ) * DMODEL + h * DHEAD;

    // ---- load Q tile (128x64, scaled by exact 1/8) ----
#pragma unroll
    for (int i = 0; i < 8; i++) {
        const int idx = i * 256 + tid;
        const int r = idx >> 4;
        const int c4 = idx & 15;
        float4 v = *(const float4*)&Qb[(size_t)(q0 + r) * DMODEL + c4 * 4];
        float* dst = &s_qp[r * AST + c4 * 4];
        dst[0] = v.x * 0.125f; dst[1] = v.y * 0.125f;
        dst[2] = v.z * 0.125f; dst[3] = v.w * 0.125f;
    }
    __syncthreads();

    // ---- preload Q fragments via ldmatrix ----
    uint32_t qf[8][4];
#pragma unroll
    for (int ks = 0; ks < 8; ks++) {
        const int row = rq + la_row16;
        ldsm_x4(qf[ks], smb_qp + (uint32_t)row * (AST * 4) + ((2 * ks + la_hb) << 4));
    }

    auto load_kv = [&](int kt, int stage) {
        const int k0 = kt * 64;
        const float* Kp = Kb + (size_t)k0 * DMODEL;
        const float* Vp = Vb + (size_t)k0 * DMODEL;
        const uint32_t so = (uint32_t)(stage * KV_F) * 4;
#pragma unroll
        for (int i = 0; i < 4; i++) {
            const int idx = i * 256 + tid;
            const int r = idx >> 4;
            const int c4 = idx & 15;
            const uint32_t off = so + (uint32_t)(r * AST + c4 * 4) * 4;
            cpasync16(smb_k + off, Kp + (size_t)r * DMODEL + c4 * 4);
            cpasync16(smb_v + off, Vp + (size_t)r * DMODEL + c4 * 4);
        }
        CP_COMMIT();
    };

    float o[8][4];
#pragma unroll
    for (int nt = 0; nt < 8; nt++)
#pragma unroll
        for (int q = 0; q < 4; q++) o[nt][q] = 0.f;
    float m0 = -1e30f, m1 = -1e30f, l0 = 0.f, l1 = 0.f;

    const int nkt = 2 * qt + 2;
    load_kv(0, 0);
    int buf = 0;

    for (int kt = 0; kt < nkt; kt++) {
        if (kt + 1 < nkt) { load_kv(kt + 1, buf ^ 1); CP_WAIT1(); }
        else              { CP_WAIT0(); }
        __syncthreads();

        const uint32_t kbyte = smb_k + (uint32_t)(buf * KV_F) * 4;
        const float* vb = s_v + buf * KV_F;

        // ---- S = Q K^T ----
        float s[8][4];
#pragma unroll
        for (int nt = 0; nt < 8; nt++)
#pragma unroll
            for (int q = 0; q < 4; q++) s[nt][q] = 0.f;

#pragma unroll
        for (int ks = 0; ks < 8; ks++) {
            uint32_t bk[8][2];
#pragma unroll
            for (int np = 0; np < 4; np++) {
                const int row = np * 16 + lb_rsub;
                uint32_t t4[4];
                ldsm_x4(t4, kbyte + (uint32_t)row * (AST * 4) + ((2 * ks + lb_hb) << 4));
                bk[2 * np][0] = t4[0]; bk[2 * np][1] = t4[1];
                bk[2 * np + 1][0] = t4[2]; bk[2 * np + 1][1] = t4[3];
            }
#pragma unroll
            for (int nt = 0; nt < 8; nt++)
                mma_tf32(s[nt], qf[ks], bk[nt]);
        }

        // ---- causal mask (global compare; only last two k-tiles touch diag) ----
        if (kt >= 2 * qt) {
            const int gq0 = q0 + rq + gro;
            const int gq1 = gq0 + 8;
#pragma unroll
            for (int nt = 0; nt < 8; nt++) {
                const int gk = kt * 64 + nt * 8 + tig * 2;
                if (gk > gq0)     s[nt][0] = -1e30f;
                if (gk + 1 > gq0) s[nt][1] = -1e30f;
                if (gk > gq1)     s[nt][2] = -1e30f;
                if (gk + 1 > gq1) s[nt][3] = -1e30f;
            }
        }

        // ---- online softmax ----
        float mx0 = -1e30f, mx1 = -1e30f;
#pragma unroll
        for (int nt = 0; nt < 8; nt++) {
            mx0 = fmaxf(mx0, fmaxf(s[nt][0], s[nt][1]));
            mx1 = fmaxf(mx1, fmaxf(s[nt][2], s[nt][3]));
        }
        mx0 = fmaxf(mx0, __shfl_xor_sync(0xffffffffu, mx0, 1));
        mx0 = fmaxf(mx0, __shfl_xor_sync(0xffffffffu, mx0, 2));
        mx1 = fmaxf(mx1, __shfl_xor_sync(0xffffffffu, mx1, 1));
        mx1 = fmaxf(mx1, __shfl_xor_sync(0xffffffffu, mx1, 2));

        const float nm0 = fmaxf(m0, mx0);
        const float nm1 = fmaxf(m1, mx1);
        const float a0 = __expf(m0 - nm0);
        const float a1 = __expf(m1 - nm1);
        m0 = nm0; m1 = nm1;

        float rs0 = 0.f, rs1 = 0.f;
#pragma unroll
        for (int nt = 0; nt < 8; nt++) {
            s[nt][0] = __expf(s[nt][0] - nm0); rs0 += s[nt][0];
            s[nt][1] = __expf(s[nt][1] - nm0); rs0 += s[nt][1];
            s[nt][2] = __expf(s[nt][2] - nm1); rs1 += s[nt][2];
            s[nt][3] = __expf(s[nt][3] - nm1); rs1 += s[nt][3];
        }
        rs0 += __shfl_xor_sync(0xffffffffu, rs0, 1);
        rs0 += __shfl_xor_sync(0xffffffffu, rs0, 2);
        rs1 += __shfl_xor_sync(0xffffffffu, rs1, 1);
        rs1 += __shfl_xor_sync(0xffffffffu, rs1, 2);
        l0 = l0 * a0 + rs0;
        l1 = l1 * a1 + rs1;

        // rescale O; stage tf32-rounded P (own warp rows only)
#pragma unroll
        for (int nt = 0; nt < 8; nt++) {
            o[nt][0] *= a0; o[nt][1] *= a0; o[nt][2] *= a1; o[nt][3] *= a1;
            *(float2*)&s_qp[(rq + gro) * AST + nt * 8 + tig * 2] =
                make_float2(roundtf(s[nt][0]), roundtf(s[nt][1]));
            *(float2*)&s_qp[(rq + gro + 8) * AST + nt * 8 + tig * 2] =
                make_float2(roundtf(s[nt][2]), roundtf(s[nt][3]));
        }
        __syncwarp();

        // ---- O += P V ----
#pragma unroll
        for (int ks = 0; ks < 8; ks++) {
            uint32_t ap[4];
            {
                const int row = rq + la_row16;
                ldsm_x4(ap, smb_qp + (uint32_t)row * (AST * 4) + ((2 * ks + la_hb) << 4));
            }
#pragma unroll
            for (int nt = 0; nt < 8; nt++) {
                uint32_t bv[2];
                bv[0] = __float_as_uint(vb[(ks * 8 + tig) * AST + nt * 8 + gro]);
                bv[1] = __float_as_uint(vb[(ks * 8 + tig + 4) * AST + nt * 8 + gro]);
                mma_tf32(o[nt], ap, bv);
            }
        }

        __syncthreads();
        buf ^= 1;
    }

    // ---- finalize + write rounded AO ----
    const float inv0 = 1.f / l0;
    const float inv1 = 1.f / l1;
    float* ao0 = g_AO + (size_t)(b * SEQ + q0 + rq + gro) * DMODEL + h * DHEAD;
    float* ao1 = g_AO + (size_t)(b * SEQ + q0 + rq + gro + 8) * DMODEL + h * DHEAD;
#pragma unroll
    for (int nt = 0; nt < 8; nt++) {
        const int cc = nt * 8 + tig * 2;
        *(float2*)&ao0[cc] = make_float2(roundtf(o[nt][0] * inv0), roundtf(o[nt][1] * inv0));
        *(float2*)&ao1[cc] = make_float2(roundtf(o[nt][2] * inv1), roundtf(o[nt][3] * inv1));
    }
}

// ---------------------------------------------------------------------------
extern "C" void kernel_launch(void* const* d_in, const int* in_sizes, int n_in,
                              void* d_out, int out_size)
{
    const float* x  = (const float*)d_in[0];
    const float* wq = (const float*)d_in[1];
    const float* wk = (const float*)d_in[2];
    const float* wv = (const float*)d_in[3];
    const float* wo = (const float*)d_in[4];
    float* out = (float*)d_out;

    cudaFuncSetAttribute(qkv_kernel,  cudaFuncAttributeMaxDynamicSharedMemorySize, GEMM_SMEM);
    cudaFuncSetAttribute(proj_kernel, cudaFuncAttributeMaxDynamicSharedMemorySize, GEMM_SMEM);
    cudaFuncSetAttribute(attn_kernel, cudaFuncAttributeMaxDynamicSharedMemorySize, ATT_SMEM);

    prep_kernel<<<(PREP_TOT + 255) / 256, 256>>>(x, wq, wk, wv, wo);
    qkv_kernel<<<dim3(DMODEL / G_BN, MTOT / G_BM, 3), 256, GEMM_SMEM>>>();
    attn_kernel<<<dim3(SEQ / 128, BHTOT), 256, ATT_SMEM>>>();
    proj_kernel<<<dim3(DMODEL / G_BN, MTOT / G_BM), 256, GEMM_SMEM>>>(out);
}

// round 10
// speedup vs baseline: 4.1654x; 1.0269x over previous
#include <cuda_runtime.h>
#include <cuda_bf16.h>
#include <cstdint>

// Problem constants
#define BATCH 4
#define SEQ   2048
#define DMODEL 1024
#define NHEADS 16
#define DHEAD 64
#define MTOT (BATCH*SEQ)          // 8192
#define BHTOT (BATCH*NHEADS)      // 64

// Scratch (device globals)
__device__ float g_Q[MTOT * DMODEL];
__device__ float g_K[MTOT * DMODEL];
__device__ float g_V[MTOT * DMODEL];
__device__ float g_AO[MTOT * DMODEL];
__device__ float g_Xr[MTOT * DMODEL];            // tf32-rounded x
__device__ float g_Wr[4][DMODEL * DMODEL];       // tf32-rounded wq,wk,wv,wo

// ---------------------------------------------------------------------------
// Helpers
// ---------------------------------------------------------------------------
__device__ __forceinline__ uint32_t smem_u32(const void* p) {
    uint32_t a;
    asm("{ .reg .u64 t; cvta.to.shared.u64 t, %1; cvt.u32.u64 %0, t; }" : "=r"(a) : "l"(p));
    return a;
}
__device__ __forceinline__ void cpasync16(uint32_t dst, const void* src) {
    asm volatile("cp.async.cg.shared.global [%0], [%1], 16;" :: "r"(dst), "l"(src));
}
#define CP_COMMIT() asm volatile("cp.async.commit_group;" ::: "memory")
#define CP_WAIT1()  asm volatile("cp.async.wait_group 1;" ::: "memory")
#define CP_WAIT0()  asm volatile("cp.async.wait_group 0;" ::: "memory")

__device__ __forceinline__ uint32_t f2tf32(float f) {
    uint32_t u;
    asm("cvt.rna.tf32.f32 %0, %1;" : "=r"(u) : "f"(f));
    return u;
}
__device__ __forceinline__ float roundtf(float f) { return __uint_as_float(f2tf32(f)); }

__device__ __forceinline__ void mma_tf32(float c[4], const uint32_t a[4], const uint32_t b[2]) {
    asm volatile("mma.sync.aligned.m16n8k8.row.col.f32.tf32.tf32.f32 "
        "{%0,%1,%2,%3}, {%4,%5,%6,%7}, {%8,%9}, {%0,%1,%2,%3};"
        : "+f"(c[0]), "+f"(c[1]), "+f"(c[2]), "+f"(c[3])
        : "r"(a[0]), "r"(a[1]), "r"(a[2]), "r"(a[3]), "r"(b[0]), "r"(b[1]));
}
__device__ __forceinline__ void ldsm_x4(uint32_t r[4], uint32_t addr) {
    asm volatile("ldmatrix.sync.aligned.m8n8.x4.shared.b16 {%0,%1,%2,%3}, [%4];"
        : "=r"(r[0]), "=r"(r[1]), "=r"(r[2]), "=r"(r[3]) : "r"(addr));
}

// ---------------------------------------------------------------------------
// Prep: round x + weights to tf32 (rna) once.
// ---------------------------------------------------------------------------
#define XN4 ((int)(MTOT * DMODEL / 4))
#define WN4 ((int)(DMODEL * DMODEL / 4))
#define PREP_TOT (XN4 + 4 * WN4)

__global__ void __launch_bounds__(256) prep_kernel(const float* __restrict__ x,
                                                   const float* __restrict__ wq,
                                                   const float* __restrict__ wk,
                                                   const float* __restrict__ wv,
                                                   const float* __restrict__ wo)
{
    const int i = blockIdx.x * 256 + threadIdx.x;
    if (i >= PREP_TOT) return;
    const float4* src;
    float4* dst;
    int off;
    if (i < XN4) {
        src = (const float4*)x; dst = (float4*)g_Xr; off = i;
    } else {
        const int j = i - XN4;
        const int w = j / WN4;
        off = j - w * WN4;
        src = (const float4*)((w == 0) ? wq : (w == 1) ? wk : (w == 2) ? wv : wo);
        dst = (float4*)g_Wr[w];
    }
    float4 v = src[off];
    v.x = roundtf(v.x); v.y = roundtf(v.y); v.z = roundtf(v.z); v.w = roundtf(v.w);
    dst[off] = v;
}

// ---------------------------------------------------------------------------
// tf32 mma.sync GEMM with ldmatrix fragment loads. (unchanged from R9)
// ---------------------------------------------------------------------------
#define G_BM 128
#define G_BN 128
#define G_BK 32
#define G_NT (DMODEL / G_BK)       // 32
#define TILE_F (G_BM * G_BK)       // 4096 floats = 16KB
#define STAGE_F (2 * TILE_F)
#define GEMM_SMEM (2 * STAGE_F * 4)  // 64 KB

template<int ROUND_OUT>
__device__ __forceinline__ void gemm_core(const float* __restrict__ A,
                                          const float* __restrict__ W,
                                          float* __restrict__ C)
{
    extern __shared__ __align__(16) float smf[];
    const uint32_t smb = smem_u32(smf);
    const int tid = threadIdx.x;
    const int wid = tid >> 5;
    const int lane = tid & 31;
    const int gro = lane >> 2;
    const int tig = lane & 3;
    const int wm = wid >> 2;
    const int wn = wid & 3;
    const int m0 = blockIdx.y * G_BM;
    const int n0 = blockIdx.x * G_BN;

    const int la_row16 = lane & 15;
    const int la_hb = lane >> 4;
    const int lb_rsub = ((lane >> 4) << 3) + (lane & 7);
    const int lb_hb = (lane >> 3) & 1;

    float acc[4][4][4];
#pragma unroll
    for (int mi = 0; mi < 4; mi++)
#pragma unroll
        for (int ni = 0; ni < 4; ni++)
#pragma unroll
            for (int q = 0; q < 4; q++) acc[mi][ni][q] = 0.f;

    auto load_tile = [&](int kt, int stage) {
        const int abase = stage * STAGE_F;
        const int bbase = abase + TILE_F;
#pragma unroll
        for (int i = 0; i < 4; i++) {
            const int idx = i * 256 + tid;
            const int row = idx >> 3;
            const int c4 = idx & 7;
            const int sw = ((c4 ^ (row & 7)) << 2);
            cpasync16(smb + (uint32_t)(abase + row * 32 + sw) * 4,
                      A + (size_t)(m0 + row) * DMODEL + kt * G_BK + c4 * 4);
            cpasync16(smb + (uint32_t)(bbase + row * 32 + sw) * 4,
                      W + (size_t)(n0 + row) * DMODEL + kt * G_BK + c4 * 4);
        }
        CP_COMMIT();
    };

    load_tile(0, 0);
    int buf = 0;

    for (int kt = 0; kt < G_NT; kt++) {
        if (kt + 1 < G_NT) { load_tile(kt + 1, buf ^ 1); CP_WAIT1(); }
        else               { CP_WAIT0(); }
        __syncthreads();

        const uint32_t abyte = smb + (uint32_t)(buf * STAGE_F) * 4;
        const uint32_t bbyte = abyte + (uint32_t)TILE_F * 4;

#pragma unroll
        for (int ks = 0; ks < 4; ks++) {
            uint32_t af[4][4], bf[4][2];
#pragma unroll
            for (int mi = 0; mi < 4; mi++) {
                const int row = wm * 64 + mi * 16 + la_row16;
                const uint32_t c = 2 * ks + la_hb;
                ldsm_x4(af[mi], abyte + (uint32_t)row * 128 + ((c ^ (row & 7)) << 4));
            }
#pragma unroll
            for (int np = 0; np < 2; np++) {
                const int row = wn * 32 + np * 16 + lb_rsub;
                const uint32_t c = 2 * ks + lb_hb;
                uint32_t t4[4];
                ldsm_x4(t4, bbyte + (uint32_t)row * 128 + ((c ^ (row & 7)) << 4));
                bf[2 * np][0] = t4[0]; bf[2 * np][1] = t4[1];
                bf[2 * np + 1][0] = t4[2]; bf[2 * np + 1][1] = t4[3];
            }
#pragma unroll
            for (int mi = 0; mi < 4; mi++)
#pragma unroll
                for (int ni = 0; ni < 4; ni++)
                    mma_tf32(acc[mi][ni], af[mi], bf[ni]);
        }
        __syncthreads();
        buf ^= 1;
    }

#pragma unroll
    for (int mi = 0; mi < 4; mi++) {
        const int r0 = m0 + wm * 64 + mi * 16 + gro;
#pragma unroll
        for (int ni = 0; ni < 4; ni++) {
            const int cc = n0 + wn * 32 + ni * 8 + tig * 2;
            float v0 = acc[mi][ni][0], v1 = acc[mi][ni][1];
            float v2 = acc[mi][ni][2], v3 = acc[mi][ni][3];
            if (ROUND_OUT) { v0 = roundtf(v0); v1 = roundtf(v1); v2 = roundtf(v2); v3 = roundtf(v3); }
            *(float2*)&C[(size_t)r0 * DMODEL + cc] = make_float2(v0, v1);
            *(float2*)&C[(size_t)(r0 + 8) * DMODEL + cc] = make_float2(v2, v3);
        }
    }
}

__global__ void __launch_bounds__(256) qkv_kernel()
{
    const float* W = g_Wr[blockIdx.z];
    float* C = (blockIdx.z == 0) ? g_Q : (blockIdx.z == 1) ? g_K : g_V;
    gemm_core<1>(g_Xr, W, C);
}

__global__ void __launch_bounds__(256) proj_kernel(float* __restrict__ out)
{
    gemm_core<0>(g_AO, g_Wr[3], out);
}

// ---------------------------------------------------------------------------
// Flash attention, tf32 mma.sync + ldmatrix, causal.
// Block: 128 q-rows x 64 k-cols per step, 256 threads (8 warps x 16 rows).
// Smem: XOR-swizzled stride-64 layout (96 KB total) -> 2 blocks/SM.
//   [Q->P: 128x64][K: 2 stages 64x64][V: 2 stages 64x64]
// ---------------------------------------------------------------------------
#define QP_F (128 * 64)             // 8192 floats
#define KV_F (64 * 64)              // 4096 floats
#define ATT_SMEM ((QP_F + 4 * KV_F) * 4)   // 98304 B

// swizzled float index for stride-64 rows
#define SWI(r, c) ((r) * 64 + ((((c) >> 2) ^ ((r) & 7)) << 2) + ((c) & 3))

__global__ void __launch_bounds__(256, 2) attn_kernel()
{
    extern __shared__ __align__(16) float sm[];
    float* s_qp = sm;                       // Q, later P (128 rows)
    float* s_k  = sm + QP_F;                // 2 stages
    float* s_v  = sm + QP_F + 2 * KV_F;     // 2 stages
    const uint32_t smb_qp = smem_u32(s_qp);
    const uint32_t smb_k  = smem_u32(s_k);
    const uint32_t smb_v  = smem_u32(s_v);

    const int tid = threadIdx.x;
    const int wid = tid >> 5;
    const int lane = tid & 31;
    const int gro = lane >> 2;
    const int tig = lane & 3;
    const int rq = wid * 16;

    const int la_row16 = lane & 15;
    const int la_hb = lane >> 4;
    const int lb_rsub = ((lane >> 4) << 3) + (lane & 7);
    const int lb_hb = (lane >> 3) & 1;

    const int qt = blockIdx.x;              // 0..15
    const int bh = blockIdx.y;
    const int q0 = qt * 128;
    const int b = bh >> 4;
    const int h = bh & 15;

    const float* Qb = g_Q + (size_t)(b * SEQ) * DMODEL + h * DHEAD;
    const float* Kb = g_K + (size_t)(b * SEQ) * DMODEL + h * DHEAD;
    const float* Vb = g_V + (size_t)(b * SEQ) * DMODEL + h * DHEAD;

    // ---- load Q tile (128x64, scaled by exact 1/8) into swizzled smem ----
#pragma unroll
    for (int i = 0; i < 8; i++) {
        const int idx = i * 256 + tid;
        const int r = idx >> 4;
        const int c4 = idx & 15;
        float4 v = *(const float4*)&Qb[(size_t)(q0 + r) * DMODEL + c4 * 4];
        float* dst = &s_qp[r * 64 + ((c4 ^ (r & 7)) << 2)];
        dst[0] = v.x * 0.125f; dst[1] = v.y * 0.125f;
        dst[2] = v.z * 0.125f; dst[3] = v.w * 0.125f;
    }
    __syncthreads();

    // ---- preload Q fragments via ldmatrix (swizzled) ----
    uint32_t qf[8][4];
#pragma unroll
    for (int ks = 0; ks < 8; ks++) {
        const int row = rq + la_row16;
        const uint32_t c = 2 * ks + la_hb;
        ldsm_x4(qf[ks], smb_qp + (uint32_t)row * 256 + ((c ^ (row & 7)) << 4));
    }

    auto load_kv = [&](int kt, int stage) {
        const int k0 = kt * 64;
        const float* Kp = Kb + (size_t)k0 * DMODEL;
        const float* Vp = Vb + (size_t)k0 * DMODEL;
        const uint32_t so = (uint32_t)(stage * KV_F) * 4;
#pragma unroll
        for (int i = 0; i < 4; i++) {
            const int idx = i * 256 + tid;
            const int r = idx >> 4;
            const int c4 = idx & 15;
            const uint32_t off = so + (uint32_t)(r * 64 + ((c4 ^ (r & 7)) << 2)) * 4;
            cpasync16(smb_k + off, Kp + (size_t)r * DMODEL + c4 * 4);
            cpasync16(smb_v + off, Vp + (size_t)r * DMODEL + c4 * 4);
        }
        CP_COMMIT();
    };

    float o[8][4];
#pragma unroll
    for (int nt = 0; nt < 8; nt++)
#pragma unroll
        for (int q = 0; q < 4; q++) o[nt][q] = 0.f;
    float m0 = -1e30f, m1 = -1e30f, l0 = 0.f, l1 = 0.f;

    const int nkt = 2 * qt + 2;
    load_kv(0, 0);
    int buf = 0;

    for (int kt = 0; kt < nkt; kt++) {
        if (kt + 1 < nkt) { load_kv(kt + 1, buf ^ 1); CP_WAIT1(); }
        else              { CP_WAIT0(); }
        __syncthreads();

        const uint32_t kbyte = smb_k + (uint32_t)(buf * KV_F) * 4;
        const float* vb = s_v + buf * KV_F;

        // ---- S = Q K^T ----
        float s[8][4];
#pragma unroll
        for (int nt = 0; nt < 8; nt++)
#pragma unroll
            for (int q = 0; q < 4; q++) s[nt][q] = 0.f;

#pragma unroll
        for (int ks = 0; ks < 8; ks++) {
            uint32_t bk[8][2];
#pragma unroll
            for (int np = 0; np < 4; np++) {
                const int row = np * 16 + lb_rsub;
                const uint32_t c = 2 * ks + lb_hb;
                uint32_t t4[4];
                ldsm_x4(t4, kbyte + (uint32_t)row * 256 + ((c ^ (row & 7)) << 4));
                bk[2 * np][0] = t4[0]; bk[2 * np][1] = t4[1];
                bk[2 * np + 1][0] = t4[2]; bk[2 * np + 1][1] = t4[3];
            }
#pragma unroll
            for (int nt = 0; nt < 8; nt++)
                mma_tf32(s[nt], qf[ks], bk[nt]);
        }

        // ---- causal mask (only last two k-tiles touch diagonal) ----
        if (kt >= 2 * qt) {
            const int gq0 = q0 + rq + gro;
            const int gq1 = gq0 + 8;
#pragma unroll
            for (int nt = 0; nt < 8; nt++) {
                const int gk = kt * 64 + nt * 8 + tig * 2;
                if (gk > gq0)     s[nt][0] = -1e30f;
                if (gk + 1 > gq0) s[nt][1] = -1e30f;
                if (gk > gq1)     s[nt][2] = -1e30f;
                if (gk + 1 > gq1) s[nt][3] = -1e30f;
            }
        }

        // ---- online softmax ----
        float mx0 = -1e30f, mx1 = -1e30f;
#pragma unroll
        for (int nt = 0; nt < 8; nt++) {
            mx0 = fmaxf(mx0, fmaxf(s[nt][0], s[nt][1]));
            mx1 = fmaxf(mx1, fmaxf(s[nt][2], s[nt][3]));
        }
        mx0 = fmaxf(mx0, __shfl_xor_sync(0xffffffffu, mx0, 1));
        mx0 = fmaxf(mx0, __shfl_xor_sync(0xffffffffu, mx0, 2));
        mx1 = fmaxf(mx1, __shfl_xor_sync(0xffffffffu, mx1, 1));
        mx1 = fmaxf(mx1, __shfl_xor_sync(0xffffffffu, mx1, 2));

        const float nm0 = fmaxf(m0, mx0);
        const float nm1 = fmaxf(m1, mx1);
        const float a0 = __expf(m0 - nm0);
        const float a1 = __expf(m1 - nm1);
        m0 = nm0; m1 = nm1;

        float rs0 = 0.f, rs1 = 0.f;
#pragma unroll
        for (int nt = 0; nt < 8; nt++) {
            s[nt][0] = __expf(s[nt][0] - nm0); rs0 += s[nt][0];
            s[nt][1] = __expf(s[nt][1] - nm0); rs0 += s[nt][1];
            s[nt][2] = __expf(s[nt][2] - nm1); rs1 += s[nt][2];
            s[nt][3] = __expf(s[nt][3] - nm1); rs1 += s[nt][3];
        }
        rs0 += __shfl_xor_sync(0xffffffffu, rs0, 1);
        rs0 += __shfl_xor_sync(0xffffffffu, rs0, 2);
        rs1 += __shfl_xor_sync(0xffffffffu, rs1, 1);
        rs1 += __shfl_xor_sync(0xffffffffu, rs1, 2);
        l0 = l0 * a0 + rs0;
        l1 = l1 * a1 + rs1;

        // rescale O; stage tf32-rounded P into swizzled smem (own warp rows)
#pragma unroll
        for (int nt = 0; nt < 8; nt++) {
            o[nt][0] *= a0; o[nt][1] *= a0; o[nt][2] *= a1; o[nt][3] *= a1;
            const int c = nt * 8 + tig * 2;
            *(float2*)&s_qp[SWI(rq + gro, c)] =
                make_float2(roundtf(s[nt][0]), roundtf(s[nt][1]));
            *(float2*)&s_qp[SWI(rq + gro + 8, c)] =
                make_float2(roundtf(s[nt][2]), roundtf(s[nt][3]));
        }
        __syncwarp();

        // ---- O += P V ----
#pragma unroll
        for (int ks = 0; ks < 8; ks++) {
            uint32_t ap[4];
            {
                const int row = rq + la_row16;
                const uint32_t c = 2 * ks + la_hb;
                ldsm_x4(ap, smb_qp + (uint32_t)row * 256 + ((c ^ (row & 7)) << 4));
            }
#pragma unroll
            for (int nt = 0; nt < 8; nt++) {
                uint32_t bv[2];
                bv[0] = __float_as_uint(vb[SWI(ks * 8 + tig, nt * 8 + gro)]);
                bv[1] = __float_as_uint(vb[SWI(ks * 8 + tig + 4, nt * 8 + gro)]);
                mma_tf32(o[nt], ap, bv);
            }
        }

        __syncthreads();
        buf ^= 1;
    }

    // ---- finalize + write rounded AO ----
    const float inv0 = 1.f / l0;
    const float inv1 = 1.f / l1;
    float* ao0 = g_AO + (size_t)(b * SEQ + q0 + rq + gro) * DMODEL + h * DHEAD;
    float* ao1 = g_AO + (size_t)(b * SEQ + q0 + rq + gro + 8) * DMODEL + h * DHEAD;
#pragma unroll
    for (int nt = 0; nt < 8; nt++) {
        const int cc = nt * 8 + tig * 2;
        *(float2*)&ao0[cc] = make_float2(roundtf(o[nt][0] * inv0), roundtf(o[nt][1] * inv0));
        *(float2*)&ao1[cc] = make_float2(roundtf(o[nt][2] * inv1), roundtf(o[nt][3] * inv1));
    }
}

// ---------------------------------------------------------------------------
extern "C" void kernel_launch(void* const* d_in, const int* in_sizes, int n_in,
                              void* d_out, int out_size)
{
    const float* x  = (const float*)d_in[0];
    const float* wq = (const float*)d_in[1];
    const float* wk = (const float*)d_in[2];
    const float* wv = (const float*)d_in[3];
    const float* wo = (const float*)d_in[4];
    float* out = (float*)d_out;

    cudaFuncSetAttribute(qkv_kernel,  cudaFuncAttributeMaxDynamicSharedMemorySize, GEMM_SMEM);
    cudaFuncSetAttribute(proj_kernel, cudaFuncAttributeMaxDynamicSharedMemorySize, GEMM_SMEM);
    cudaFuncSetAttribute(attn_kernel, cudaFuncAttributeMaxDynamicSharedMemorySize, ATT_SMEM);

    prep_kernel<<<(PREP_TOT + 255) / 256, 256>>>(x, wq, wk, wv, wo);
    qkv_kernel<<<dim3(DMODEL / G_BN, MTOT / G_BM, 3), 256, GEMM_SMEM>>>();
    attn_kernel<<<dim3(SEQ / 128, BHTOT), 256, ATT_SMEM>>>();
    proj_kernel<<<dim3(DMODEL / G_BN, MTOT / G_BM), 256, GEMM_SMEM>>>(out);
}